// round 2
// baseline (speedup 1.0000x reference)
#include <cuda_runtime.h>
#include <cstdint>

// Problem constants
#define L_Q  128
#define N_B  8
#define S_P  16384
#define C_D  256
#define SN_ROWS (S_P * N_B)   // 131072
#define LN_ROWS (L_Q * N_B)   // 1024

// Scratch (static device arrays; allocation inside kernel_launch is forbidden)
__device__ float g_qproj[LN_ROWS * C_D];                 // 1 MB
__device__ float g_knorm[SN_ROWS * C_D];                 // 134 MB
__device__ unsigned long long g_argmax[LN_ROWS];         // packed (mapped_logit<<32)|~s

// ---------------- f32x2 packed-math helpers ----------------
static __device__ __forceinline__ unsigned long long pk2(float x) {
    unsigned long long r;
    asm("mov.b64 %0, {%1, %2};" : "=l"(r) : "f"(x), "f"(x));
    return r;
}
static __device__ __forceinline__ void upk2(unsigned long long v, float& a, float& b) {
    asm("mov.b64 {%0, %1}, %2;" : "=f"(a), "=f"(b) : "l"(v));
}
static __device__ __forceinline__ unsigned long long ffma2(unsigned long long a,
                                                           unsigned long long b,
                                                           unsigned long long c) {
    unsigned long long d;
    asm("fma.rn.f32x2 %0, %1, %2, %3;" : "=l"(d) : "l"(a), "l"(b), "l"(c));
    return d;
}

// ---------------- init ----------------
__global__ void init_argmax_kernel() {
    int i = blockIdx.x * blockDim.x + threadIdx.x;
    if (i < LN_ROWS) g_argmax[i] = 0ull;
}

// ---------------- GEMM: out[row][j] = (A1[row]+A2[row]) . W[j] + bias[j]
// rows-per-CTA = 64, cols = 256 (full), K = 256.
// NORM=true  -> L2-normalize each output row, write to g_knorm
// NORM=false -> write raw to g_qproj
template <bool NORM>
__global__ __launch_bounds__(256, 2) void gemm_rows_kernel(
    const float* __restrict__ A1, const float* __restrict__ A2,
    const float* __restrict__ W,  const float* __restrict__ bias)
{
    __shared__ float As[16 * 68];    // [k][row], padded
    __shared__ float Ws[16 * 260];   // [k][col], padded (260 % 4 == 0 for LDS.128)

    const int t  = threadIdx.x;
    const int tx = t & 31;
    const int ty = t >> 5;
    const int row0 = blockIdx.x * 64;

    unsigned long long acc[8][4];
#pragma unroll
    for (int r = 0; r < 8; ++r)
#pragma unroll
        for (int p = 0; p < 4; ++p) acc[r][p] = 0ull;

    const int arow = t >> 2;   // 0..63
    const int akq  = t & 3;    // 0..3

    for (int kt = 0; kt < 256; kt += 16) {
        // stage A tile (64 rows x 16 k), transposed into As[k][row]
        {
            const float4 a1 = *(const float4*)&A1[(size_t)(row0 + arow) * 256 + kt + akq * 4];
            const float4 a2 = *(const float4*)&A2[(size_t)(row0 + arow) * 256 + kt + akq * 4];
            As[(akq * 4 + 0) * 68 + arow] = a1.x + a2.x;
            As[(akq * 4 + 1) * 68 + arow] = a1.y + a2.y;
            As[(akq * 4 + 2) * 68 + arow] = a1.z + a2.z;
            As[(akq * 4 + 3) * 68 + arow] = a1.w + a2.w;
        }
        // stage W tile (256 cols x 16 k), transposed into Ws[k][col]
#pragma unroll
        for (int p = 0; p < 4; ++p) {
            int id = t + p * 256;
            int j  = id >> 2;
            int kq = id & 3;
            const float4 w = *(const float4*)&W[(size_t)j * 256 + kt + kq * 4];
            Ws[(kq * 4 + 0) * 260 + j] = w.x;
            Ws[(kq * 4 + 1) * 260 + j] = w.y;
            Ws[(kq * 4 + 2) * 260 + j] = w.z;
            Ws[(kq * 4 + 3) * 260 + j] = w.w;
        }
        __syncthreads();
#pragma unroll
        for (int kk = 0; kk < 16; ++kk) {
            const ulonglong2 b0 = *(const ulonglong2*)&Ws[kk * 260 + tx * 4];
            const ulonglong2 b1 = *(const ulonglong2*)&Ws[kk * 260 + 128 + tx * 4];
#pragma unroll
            for (int r = 0; r < 8; ++r) {
                const int rl = (r < 4) ? (ty * 4 + r) : (32 + ty * 4 + (r - 4));
                const unsigned long long ap = pk2(As[kk * 68 + rl]);
                acc[r][0] = ffma2(ap, b0.x, acc[r][0]);
                acc[r][1] = ffma2(ap, b0.y, acc[r][1]);
                acc[r][2] = ffma2(ap, b1.x, acc[r][2]);
                acc[r][3] = ffma2(ap, b1.y, acc[r][3]);
            }
        }
        __syncthreads();
    }

    float* __restrict__ out = NORM ? g_knorm : g_qproj;

    float bv_[8];
#pragma unroll
    for (int i = 0; i < 4; ++i) {
        bv_[i]     = bias[tx * 4 + i];
        bv_[4 + i] = bias[128 + tx * 4 + i];
    }

#pragma unroll
    for (int r = 0; r < 8; ++r) {
        float c[8];
        upk2(acc[r][0], c[0], c[1]);
        upk2(acc[r][1], c[2], c[3]);
        upk2(acc[r][2], c[4], c[5]);
        upk2(acc[r][3], c[6], c[7]);
#pragma unroll
        for (int i = 0; i < 8; ++i) c[i] += bv_[i];

        if (NORM) {
            float ss = 0.f;
#pragma unroll
            for (int i = 0; i < 8; ++i) ss += c[i] * c[i];
#pragma unroll
            for (int off = 16; off > 0; off >>= 1)
                ss += __shfl_xor_sync(0xffffffffu, ss, off);
            const float sc = 1.0f / fmaxf(sqrtf(ss), 1e-12f);
#pragma unroll
            for (int i = 0; i < 8; ++i) c[i] *= sc;
        }

        const int rl = (r < 4) ? (ty * 4 + r) : (32 + ty * 4 + (r - 4));
        float* o = &out[(size_t)(row0 + rl) * 256];
        *(float4*)&o[tx * 4]       = make_float4(c[0], c[1], c[2], c[3]);
        *(float4*)&o[128 + tx * 4] = make_float4(c[4], c[5], c[6], c[7]);
    }
}

// ---------------- logits + running argmax ----------------
// CTA: (s-tile of 128, batch n). logits[l][s] = qproj[l,n] . knorm[s,n], K=256.
__global__ __launch_bounds__(256, 2) void logits_argmax_kernel()
{
    __shared__ float Qs[16 * 132];  // [k][l]
    __shared__ float Ks[16 * 132];  // [k][s]

    const int t  = threadIdx.x;
    const int tx = t & 31;
    const int ty = t >> 5;
    const int s0 = blockIdx.x * 128;
    const int n  = blockIdx.y;

    unsigned long long acc[16][2];
#pragma unroll
    for (int r = 0; r < 16; ++r) { acc[r][0] = 0ull; acc[r][1] = 0ull; }

    for (int kt = 0; kt < 256; kt += 16) {
#pragma unroll
        for (int p = 0; p < 2; ++p) {
            const int id = t + p * 256;
            const int rr = id >> 2;
            const int kq = id & 3;
            const float4 q = *(const float4*)&g_qproj[(size_t)(rr * 8 + n) * 256 + kt + kq * 4];
            Qs[(kq * 4 + 0) * 132 + rr] = q.x;
            Qs[(kq * 4 + 1) * 132 + rr] = q.y;
            Qs[(kq * 4 + 2) * 132 + rr] = q.z;
            Qs[(kq * 4 + 3) * 132 + rr] = q.w;
            const float4 k = *(const float4*)&g_knorm[(size_t)((s0 + rr) * 8 + n) * 256 + kt + kq * 4];
            Ks[(kq * 4 + 0) * 132 + rr] = k.x;
            Ks[(kq * 4 + 1) * 132 + rr] = k.y;
            Ks[(kq * 4 + 2) * 132 + rr] = k.z;
            Ks[(kq * 4 + 3) * 132 + rr] = k.w;
        }
        __syncthreads();
#pragma unroll
        for (int kk = 0; kk < 16; ++kk) {
            const ulonglong2 b = *(const ulonglong2*)&Ks[kk * 132 + tx * 4];
#pragma unroll
            for (int g = 0; g < 4; ++g)
#pragma unroll
                for (int r = 0; r < 4; ++r) {
                    const unsigned long long ap = pk2(Qs[kk * 132 + g * 32 + ty * 4 + r]);
                    acc[g * 4 + r][0] = ffma2(ap, b.x, acc[g * 4 + r][0]);
                    acc[g * 4 + r][1] = ffma2(ap, b.y, acc[g * 4 + r][1]);
                }
        }
        __syncthreads();
    }

    // argmax epilogue: each warp (fixed ty) owns 16 l-rows fully across its lanes.
#pragma unroll
    for (int q = 0; q < 16; ++q) {
        float c[4];
        upk2(acc[q][0], c[0], c[1]);
        upk2(acc[q][1], c[2], c[3]);
        unsigned long long kmax = 0ull;
#pragma unroll
        for (int i = 0; i < 4; ++i) {
            unsigned m = __float_as_uint(c[i]);
            m = (m & 0x80000000u) ? ~m : (m | 0x80000000u);   // order-preserving map
            const unsigned sidx = (unsigned)(s0 + tx * 4 + i);
            const unsigned long long key =
                ((unsigned long long)m << 32) | (unsigned long long)(0xFFFFFFFFu - sidx);
            if (key > kmax) kmax = key;
        }
#pragma unroll
        for (int off = 16; off > 0; off >>= 1) {
            const unsigned long long o = __shfl_xor_sync(0xffffffffu, kmax, off);
            if (o > kmax) kmax = o;
        }
        if (tx == 0) {
            const int lg = (q >> 2) * 32 + ty * 4 + (q & 3);
            atomicMax(&g_argmax[lg * 8 + n], kmax);
        }
    }
}

// ---------------- finalize: gather + v_proj(selected only) + Wo + residual + LN
__global__ __launch_bounds__(256) void finalize_kernel(
    const float* __restrict__ tgt,   const float* __restrict__ memory,
    const float* __restrict__ pos,
    const float* __restrict__ Wp,    const float* __restrict__ bp,
    const float* __restrict__ Wv,    const float* __restrict__ bv,
    const float* __restrict__ Wo,    const float* __restrict__ bo,
    const float* __restrict__ gamma, const float* __restrict__ beta,
    float* __restrict__ out)
{
    __shared__ float a[256];
    __shared__ float tmp[256];
    __shared__ float red[8];
    __shared__ int   s_sel;
    __shared__ float mu_s, var_s;

    const int t    = threadIdx.x;
    const int pair = blockIdx.x;           // = l*8 + n
    const int lane = t & 31, wid = t >> 5;

    if (t == 0) {
        const unsigned long long key = g_argmax[pair];
        s_sel = (int)(0xFFFFFFFFu - (unsigned)(key & 0xFFFFFFFFull));
    }
    __syncthreads();

    const int n    = pair & 7;
    const int rowk = s_sel * 8 + n;
    a[t] = memory[(size_t)rowk * 256 + t] + pos[(size_t)rowk * 256 + t];
    __syncthreads();

    // kp = a . Wp^T + bp
    float acc = bp[t];
    {
        const float4* w4 = (const float4*)&Wp[(size_t)t * 256];
#pragma unroll 8
        for (int k = 0; k < 64; ++k) {
            const float4 w = w4[k];
            acc += a[k * 4 + 0] * w.x + a[k * 4 + 1] * w.y
                 + a[k * 4 + 2] * w.z + a[k * 4 + 3] * w.w;
        }
    }
    tmp[t] = acc;
    __syncthreads();

    // v = kp . Wv^T + bv
    acc = bv[t];
    {
        const float4* w4 = (const float4*)&Wv[(size_t)t * 256];
#pragma unroll 8
        for (int k = 0; k < 64; ++k) {
            const float4 w = w4[k];
            acc += tmp[k * 4 + 0] * w.x + tmp[k * 4 + 1] * w.y
                 + tmp[k * 4 + 2] * w.z + tmp[k * 4 + 3] * w.w;
        }
    }
    a[t] = acc;        // reuse a[] for v (first loop's reads completed before tmp sync)
    __syncthreads();

    // upd = v . Wo^T + bo ; x = tgt + upd
    acc = bo[t];
    {
        const float4* w4 = (const float4*)&Wo[(size_t)t * 256];
#pragma unroll 8
        for (int k = 0; k < 64; ++k) {
            const float4 w = w4[k];
            acc += a[k * 4 + 0] * w.x + a[k * 4 + 1] * w.y
                 + a[k * 4 + 2] * w.z + a[k * 4 + 3] * w.w;
        }
    }
    const float x = tgt[(size_t)pair * 256 + t] + acc;

    // two-pass LayerNorm over 256 values
    float s = x;
#pragma unroll
    for (int off = 16; off > 0; off >>= 1) s += __shfl_xor_sync(0xffffffffu, s, off);
    if (lane == 0) red[wid] = s;
    __syncthreads();
    if (t == 0) {
        float tot = 0.f;
#pragma unroll
        for (int i = 0; i < 8; ++i) tot += red[i];
        mu_s = tot * (1.0f / 256.0f);
    }
    __syncthreads();
    const float mu = mu_s;
    const float d  = x - mu;
    float s2 = d * d;
#pragma unroll
    for (int off = 16; off > 0; off >>= 1) s2 += __shfl_xor_sync(0xffffffffu, s2, off);
    __syncthreads();               // red[] reuse
    if (lane == 0) red[wid] = s2;
    __syncthreads();
    if (t == 0) {
        float tot = 0.f;
#pragma unroll
        for (int i = 0; i < 8; ++i) tot += red[i];
        var_s = tot * (1.0f / 256.0f);
    }
    __syncthreads();

    const float rstd = rsqrtf(var_s + 1e-5f);
    out[(size_t)pair * 256 + t] = d * rstd * gamma[t] + beta[t];
}

// ---------------- launch ----------------
extern "C" void kernel_launch(void* const* d_in, const int* in_sizes, int n_in,
                              void* d_out, int out_size)
{
    const float* tgt       = (const float*)d_in[0];
    const float* memory    = (const float*)d_in[1];
    const float* pos       = (const float*)d_in[2];
    const float* query_pos = (const float*)d_in[3];
    const float* Wq        = (const float*)d_in[4];
    const float* bq        = (const float*)d_in[5];
    const float* Wp        = (const float*)d_in[6];
    const float* bp        = (const float*)d_in[7];
    const float* Wv        = (const float*)d_in[8];
    const float* bv        = (const float*)d_in[9];
    const float* Wo        = (const float*)d_in[10];
    const float* bo        = (const float*)d_in[11];
    const float* gamma     = (const float*)d_in[12];
    const float* beta      = (const float*)d_in[13];
    float* out             = (float*)d_out;

    init_argmax_kernel<<<1, 1024>>>();
    // q_proj = (tgt + query_pos) @ Wq^T + bq           -> g_qproj (1024 x 256)
    gemm_rows_kernel<false><<<LN_ROWS / 64, 256>>>(tgt, query_pos, Wq, bq);
    // k_norm = normalize((memory + pos) @ Wp^T + bp)   -> g_knorm (131072 x 256)
    gemm_rows_kernel<true><<<SN_ROWS / 64, 256>>>(memory, pos, Wp, bp);
    // logits + argmax
    logits_argmax_kernel<<<dim3(S_P / 128, N_B), 256>>>();
    // gather + lazy v_proj + output projection + residual + LayerNorm
    finalize_kernel<<<LN_ROWS, 256>>>(tgt, memory, pos, Wp, bp, Wv, bv, Wo, bo,
                                      gamma, beta, out);
}

// round 3
// speedup vs baseline: 1.4845x; 1.4845x over previous
#include <cuda_runtime.h>
#include <cuda_bf16.h>
#include <cstdint>

// Problem constants
#define L_Q  128
#define N_B  8
#define S_P  16384
#define C_D  256
#define SN_ROWS (S_P * N_B)   // 131072
#define LN_ROWS (L_Q * N_B)   // 1024
#define MARGIN  0.30f
#define CAND_CAP (1u << 20)

// ---------------- scratch ----------------
__device__ float          g_qproj[LN_ROWS * C_D];            // exact fp32 q_proj
__device__ __nv_bfloat16  g_qb[LN_ROWS * C_D];               // bf16 q_proj
__device__ __nv_bfloat16  g_wpb[C_D * C_D];                  // bf16 Wp
__device__ __nv_bfloat16  g_kn[(size_t)SN_ROWS * C_D];       // bf16 normalized k_proj (67MB)
__device__ float          g_logits[(size_t)N_B * S_P * L_Q]; // approx logits (64MB), [n][s][l]
__device__ unsigned       g_amax[LN_ROWS];                   // mapped-float approx max
__device__ unsigned       g_cand[CAND_CAP];                  // packed (s<<10)|(l<<3)|n
__device__ unsigned       g_ncand;
__device__ unsigned long long g_argmax[LN_ROWS];             // packed (mapped_exact<<32)|~s

// ---------------- helpers ----------------
static __device__ __forceinline__ unsigned fmap(float x) {
    unsigned m = __float_as_uint(x);
    return (m & 0x80000000u) ? ~m : (m | 0x80000000u);
}
static __device__ __forceinline__ float funmap(unsigned u) {
    return __uint_as_float((u & 0x80000000u) ? (u ^ 0x80000000u) : ~u);
}
static __device__ __forceinline__ void mma_bf16(float c[4], const unsigned a[4],
                                                unsigned b0, unsigned b1) {
    asm volatile("mma.sync.aligned.m16n8k16.row.col.f32.bf16.bf16.f32 "
                 "{%0,%1,%2,%3}, {%4,%5,%6,%7}, {%8,%9}, {%0,%1,%2,%3};"
                 : "+f"(c[0]), "+f"(c[1]), "+f"(c[2]), "+f"(c[3])
                 : "r"(a[0]), "r"(a[1]), "r"(a[2]), "r"(a[3]), "r"(b0), "r"(b1));
}

// ---------------- K0: init ----------------
__global__ void init_kernel() {
    int i = blockIdx.x * blockDim.x + threadIdx.x;
    if (i < LN_ROWS) { g_amax[i] = 0u; g_argmax[i] = 0ull; }
    if (i == 0) g_ncand = 0u;
}

// ---------------- K0b: Wp -> bf16 ----------------
__global__ void wpconv_kernel(const float* __restrict__ Wp) {
    int i = blockIdx.x * blockDim.x + threadIdx.x;   // 65536
    g_wpb[i] = __float2bfloat16(Wp[i]);
}

// ---------------- K1: exact fp32 q_proj (+ bf16 copy) ----------------
__global__ __launch_bounds__(256) void qproj_kernel(
    const float* __restrict__ tgt, const float* __restrict__ qpos,
    const float* __restrict__ Wq,  const float* __restrict__ bq)
{
    __shared__ float a_s[8][256];
    const int t  = threadIdx.x;
    const int r0 = blockIdx.x * 8;
#pragma unroll
    for (int r = 0; r < 8; ++r)
        a_s[r][t] = tgt[(size_t)(r0 + r) * 256 + t] + qpos[(size_t)(r0 + r) * 256 + t];
    __syncthreads();
    float acc[8];
#pragma unroll
    for (int r = 0; r < 8; ++r) acc[r] = bq[t];
    const float4* w4 = (const float4*)&Wq[(size_t)t * 256];
#pragma unroll 4
    for (int k4 = 0; k4 < 64; ++k4) {
        const float4 w = w4[k4];
#pragma unroll
        for (int r = 0; r < 8; ++r) {
            const float4 a = *(const float4*)&a_s[r][k4 * 4];
            acc[r] += a.x * w.x + a.y * w.y + a.z * w.z + a.w * w.w;
        }
    }
#pragma unroll
    for (int r = 0; r < 8; ++r) {
        g_qproj[(size_t)(r0 + r) * 256 + t] = acc[r];
        g_qb[(size_t)(r0 + r) * 256 + t]    = __float2bfloat16(acc[r]);
    }
}

// ---------------- K2: bf16 MMA k_proj + L2-normalize -> g_kn ----------------
// CTA tile: 64 rows (s*8+n flattened) x 256 cols, K=256 in chunks of 32.
// 8 warps: wm = wid&1 (M 32 each), wn = wid>>1 (N 64 each).
__global__ __launch_bounds__(256) void kp_gemm_kernel(
    const float* __restrict__ mem, const float* __restrict__ pos,
    const float* __restrict__ bp)
{
    __shared__ __nv_bfloat16 As[64 * 40];
    __shared__ __nv_bfloat16 Bs[256 * 40];
    __shared__ float rowss[64];
    __shared__ float bsm[256];

    const int t = threadIdx.x, lane = t & 31, wid = t >> 5;
    const int g = lane >> 2, tid4 = lane & 3;
    const int wm = wid & 1, wn = wid >> 1;
    const int row0 = blockIdx.x * 64;

    if (t < 64) rowss[t] = 0.f;
    bsm[t] = bp[t];

    float acc[2][8][4];
#pragma unroll
    for (int mf = 0; mf < 2; ++mf)
#pragma unroll
        for (int nf = 0; nf < 8; ++nf)
#pragma unroll
            for (int c = 0; c < 4; ++c) acc[mf][nf][c] = 0.f;

    for (int kt = 0; kt < 256; kt += 32) {
        __syncthreads();
        // stage A (64x32 fp32 -> bf16), 2 float4 pairs per thread
#pragma unroll
        for (int i = 0; i < 2; ++i) {
            const int q  = t + i * 256;         // 0..511
            const int r  = q >> 3, c4 = q & 7;
            const float4 m4 = *(const float4*)&mem[(size_t)(row0 + r) * 256 + kt + c4 * 4];
            const float4 p4 = *(const float4*)&pos[(size_t)(row0 + r) * 256 + kt + c4 * 4];
            __nv_bfloat162* dst = (__nv_bfloat162*)&As[r * 40 + c4 * 4];
            dst[0] = __floats2bfloat162_rn(m4.x + p4.x, m4.y + p4.y);
            dst[1] = __floats2bfloat162_rn(m4.z + p4.z, m4.w + p4.w);
        }
        // stage B (256x32 bf16) from g_wpb
#pragma unroll
        for (int i = 0; i < 4; ++i) {
            const int q = t + i * 256;          // 0..1023
            const int r = q >> 2, kq = q & 3;
            *(uint4*)&Bs[r * 40 + kq * 8] =
                *(const uint4*)&g_wpb[(size_t)r * 256 + kt + kq * 8];
        }
        __syncthreads();
#pragma unroll
        for (int k2 = 0; k2 < 2; ++k2) {
            unsigned a[2][4];
#pragma unroll
            for (int mf = 0; mf < 2; ++mf) {
                const int r = wm * 32 + mf * 16;
                a[mf][0] = *(const unsigned*)&As[(r + g)     * 40 + k2 * 16 + 2 * tid4];
                a[mf][1] = *(const unsigned*)&As[(r + g + 8) * 40 + k2 * 16 + 2 * tid4];
                a[mf][2] = *(const unsigned*)&As[(r + g)     * 40 + k2 * 16 + 8 + 2 * tid4];
                a[mf][3] = *(const unsigned*)&As[(r + g + 8) * 40 + k2 * 16 + 8 + 2 * tid4];
            }
#pragma unroll
            for (int nf = 0; nf < 8; ++nf) {
                const int c = wn * 64 + nf * 8 + g;
                const unsigned b0 = *(const unsigned*)&Bs[c * 40 + k2 * 16 + 2 * tid4];
                const unsigned b1 = *(const unsigned*)&Bs[c * 40 + k2 * 16 + 8 + 2 * tid4];
                mma_bf16(acc[0][nf], a[0], b0, b1);
                mma_bf16(acc[1][nf], a[1], b0, b1);
            }
        }
    }

    // epilogue: per-row sum of squares (bias added)
#pragma unroll
    for (int mf = 0; mf < 2; ++mf) {
        float ss0 = 0.f, ss1 = 0.f;
#pragma unroll
        for (int nf = 0; nf < 8; ++nf) {
            const int c = wn * 64 + nf * 8 + 2 * tid4;
            const float b0v = bsm[c], b1v = bsm[c + 1];
            const float v00 = acc[mf][nf][0] + b0v, v01 = acc[mf][nf][1] + b1v;
            const float v10 = acc[mf][nf][2] + b0v, v11 = acc[mf][nf][3] + b1v;
            ss0 += v00 * v00 + v01 * v01;
            ss1 += v10 * v10 + v11 * v11;
        }
        ss0 += __shfl_xor_sync(0xffffffffu, ss0, 1);
        ss0 += __shfl_xor_sync(0xffffffffu, ss0, 2);
        ss1 += __shfl_xor_sync(0xffffffffu, ss1, 1);
        ss1 += __shfl_xor_sync(0xffffffffu, ss1, 2);
        if (tid4 == 0) {
            atomicAdd(&rowss[wm * 32 + mf * 16 + g], ss0);
            atomicAdd(&rowss[wm * 32 + mf * 16 + g + 8], ss1);
        }
    }
    __syncthreads();
#pragma unroll
    for (int mf = 0; mf < 2; ++mf) {
        const int r0l = wm * 32 + mf * 16 + g, r1l = r0l + 8;
        const float inv0 = 1.f / fmaxf(sqrtf(rowss[r0l]), 1e-12f);
        const float inv1 = 1.f / fmaxf(sqrtf(rowss[r1l]), 1e-12f);
#pragma unroll
        for (int nf = 0; nf < 8; ++nf) {
            const int c = wn * 64 + nf * 8 + 2 * tid4;
            const float b0v = bsm[c], b1v = bsm[c + 1];
            *(__nv_bfloat162*)&g_kn[(size_t)(row0 + r0l) * 256 + c] =
                __floats2bfloat162_rn((acc[mf][nf][0] + b0v) * inv0,
                                      (acc[mf][nf][1] + b1v) * inv0);
            *(__nv_bfloat162*)&g_kn[(size_t)(row0 + r1l) * 256 + c] =
                __floats2bfloat162_rn((acc[mf][nf][2] + b0v) * inv1,
                                      (acc[mf][nf][3] + b1v) * inv1);
        }
    }
}

// ---------------- K3: bf16 MMA approx logits + per-(l,n) approx max ----------------
// CTA: (s-tile 128, n). M=s(128): wm=wid&3; N=l(128): wn=wid>>2.
__global__ __launch_bounds__(256) void logits_pref_kernel()
{
    __shared__ __nv_bfloat16 As[128 * 40];   // kn rows
    __shared__ __nv_bfloat16 Bs[128 * 40];   // q rows
    __shared__ unsigned amax_s[128];

    const int t = threadIdx.x, lane = t & 31, wid = t >> 5;
    const int g = lane >> 2, tid4 = lane & 3;
    const int wm = wid & 3, wn = wid >> 2;
    const int s0 = blockIdx.x * 128;
    const int n  = blockIdx.y;

    if (t < 128) amax_s[t] = 0u;

    float acc[2][8][4];
#pragma unroll
    for (int mf = 0; mf < 2; ++mf)
#pragma unroll
        for (int nf = 0; nf < 8; ++nf)
#pragma unroll
            for (int c = 0; c < 4; ++c) acc[mf][nf][c] = 0.f;

    for (int kt = 0; kt < 256; kt += 32) {
        __syncthreads();
#pragma unroll
        for (int i = 0; i < 2; ++i) {
            const int q = t + i * 256;    // 0..511
            const int r = q >> 2, kq = q & 3;
            *(uint4*)&As[r * 40 + kq * 8] =
                *(const uint4*)&g_kn[(size_t)((s0 + r) * 8 + n) * 256 + kt + kq * 8];
            *(uint4*)&Bs[r * 40 + kq * 8] =
                *(const uint4*)&g_qb[(size_t)(r * 8 + n) * 256 + kt + kq * 8];
        }
        __syncthreads();
#pragma unroll
        for (int k2 = 0; k2 < 2; ++k2) {
            unsigned a[2][4];
#pragma unroll
            for (int mf = 0; mf < 2; ++mf) {
                const int r = wm * 32 + mf * 16;
                a[mf][0] = *(const unsigned*)&As[(r + g)     * 40 + k2 * 16 + 2 * tid4];
                a[mf][1] = *(const unsigned*)&As[(r + g + 8) * 40 + k2 * 16 + 2 * tid4];
                a[mf][2] = *(const unsigned*)&As[(r + g)     * 40 + k2 * 16 + 8 + 2 * tid4];
                a[mf][3] = *(const unsigned*)&As[(r + g + 8) * 40 + k2 * 16 + 8 + 2 * tid4];
            }
#pragma unroll
            for (int nf = 0; nf < 8; ++nf) {
                const int c = wn * 64 + nf * 8 + g;
                const unsigned b0 = *(const unsigned*)&Bs[c * 40 + k2 * 16 + 2 * tid4];
                const unsigned b1 = *(const unsigned*)&Bs[c * 40 + k2 * 16 + 8 + 2 * tid4];
                mma_bf16(acc[0][nf], a[0], b0, b1);
                mma_bf16(acc[1][nf], a[1], b0, b1);
            }
        }
    }

    // write approx logits [n][s][l]
#pragma unroll
    for (int mf = 0; mf < 2; ++mf) {
        const int sr0 = wm * 32 + mf * 16 + g, sr1 = sr0 + 8;
#pragma unroll
        for (int nf = 0; nf < 8; ++nf) {
            const int lc = wn * 64 + nf * 8 + 2 * tid4;
            *(float2*)&g_logits[((size_t)n * S_P + s0 + sr0) * 128 + lc] =
                make_float2(acc[mf][nf][0], acc[mf][nf][1]);
            *(float2*)&g_logits[((size_t)n * S_P + s0 + sr1) * 128 + lc] =
                make_float2(acc[mf][nf][2], acc[mf][nf][3]);
        }
    }
    // per-l max over this CTA's 128 s
#pragma unroll
    for (int nf = 0; nf < 8; ++nf) {
        float m0 = fmaxf(fmaxf(acc[0][nf][0], acc[0][nf][2]),
                         fmaxf(acc[1][nf][0], acc[1][nf][2]));
        float m1 = fmaxf(fmaxf(acc[0][nf][1], acc[0][nf][3]),
                         fmaxf(acc[1][nf][1], acc[1][nf][3]));
#pragma unroll
        for (int off = 4; off < 32; off <<= 1) {
            m0 = fmaxf(m0, __shfl_xor_sync(0xffffffffu, m0, off));
            m1 = fmaxf(m1, __shfl_xor_sync(0xffffffffu, m1, off));
        }
        if (lane < 4) {
            const int lc = wn * 64 + nf * 8 + 2 * lane;
            atomicMax(&amax_s[lc],     fmap(m0));
            atomicMax(&amax_s[lc + 1], fmap(m1));
        }
    }
    __syncthreads();
    if (t < 128) atomicMax(&g_amax[t * 8 + n], amax_s[t]);
}

// ---------------- K4: collect candidates within MARGIN of approx max ----------------
__global__ __launch_bounds__(256) void collect_kernel()
{
    __shared__ float thr_s[LN_ROWS];
    const int t = threadIdx.x;
    for (int i = t; i < LN_ROWS; i += 256) thr_s[i] = funmap(g_amax[i]) - MARGIN;
    __syncthreads();
    const int total = (N_B * S_P * L_Q) / 4;  // float4 items
    for (int idx = blockIdx.x * 256 + t; idx < total; idx += gridDim.x * 256) {
        const float4 v = *(const float4*)&g_logits[(size_t)idx * 4];
        const int base = idx * 4;
        const int l  = base & 127;
        const int sn = base >> 7;
        const int s  = sn & (S_P - 1);
        const int n  = sn >> 14;
        const float* vp = &v.x;
#pragma unroll
        for (int j = 0; j < 4; ++j) {
            if (vp[j] >= thr_s[(l + j) * 8 + n]) {
                const unsigned p = atomicAdd(&g_ncand, 1u);
                if (p < CAND_CAP)
                    g_cand[p] = ((unsigned)s << 10) | ((unsigned)(l + j) << 3) | (unsigned)n;
            }
        }
    }
}

// ---------------- K5: exact fp32 rescore of candidates ----------------
__global__ __launch_bounds__(256) void rescore_kernel(
    const float* __restrict__ mem, const float* __restrict__ pos,
    const float* __restrict__ Wp,  const float* __restrict__ bp)
{
    __shared__ float a_s[8][256];
    __shared__ float q_s[8][256];
    __shared__ unsigned cinfo[8];
    __shared__ float rss[8], rqd[8];
    __shared__ unsigned count_s;

    const int t = threadIdx.x, lane = t & 31, wid = t >> 5;
    if (t == 0) count_s = min(g_ncand, CAND_CAP);
    __syncthreads();
    const unsigned count = count_s;

    for (unsigned chunk = blockIdx.x; chunk * 8u < count; chunk += gridDim.x) {
        __syncthreads();
#pragma unroll
        for (int ci = 0; ci < 8; ++ci) {
            const unsigned c = chunk * 8u + ci;
            const unsigned packed = g_cand[(c < count) ? c : chunk * 8u];
            const unsigned s = packed >> 10, n = packed & 7u;
            a_s[ci][t] = mem[((size_t)s * 8 + n) * 256 + t]
                       + pos[((size_t)s * 8 + n) * 256 + t];
            const unsigned l = (packed >> 3) & 127u;
            q_s[ci][t] = g_qproj[((size_t)l * 8 + n) * 256 + t];
            if (t == ci) cinfo[ci] = packed;
        }
        __syncthreads();

        float acc[8];
#pragma unroll
        for (int ci = 0; ci < 8; ++ci) acc[ci] = bp[t];
        const float4* w4 = (const float4*)&Wp[(size_t)t * 256];
#pragma unroll 4
        for (int k4 = 0; k4 < 64; ++k4) {
            const float4 w = w4[k4];
#pragma unroll
            for (int ci = 0; ci < 8; ++ci) {
                const float4 a = *(const float4*)&a_s[ci][k4 * 4];
                acc[ci] += a.x * w.x + a.y * w.y + a.z * w.z + a.w * w.w;
            }
        }

        for (int ci = 0; ci < 8; ++ci) {
            const float kp = acc[ci];
            float ss = kp * kp;
            float qd = q_s[ci][t] * kp;
#pragma unroll
            for (int off = 16; off > 0; off >>= 1) {
                ss += __shfl_xor_sync(0xffffffffu, ss, off);
                qd += __shfl_xor_sync(0xffffffffu, qd, off);
            }
            __syncthreads();
            if (lane == 0) { rss[wid] = ss; rqd[wid] = qd; }
            __syncthreads();
            if (t == 0) {
                const unsigned c = chunk * 8u + ci;
                if (c < count) {
                    float S = 0.f, Q = 0.f;
#pragma unroll
                    for (int w = 0; w < 8; ++w) { S += rss[w]; Q += rqd[w]; }
                    const float logit = Q / fmaxf(sqrtf(S), 1e-12f);
                    const unsigned packed = cinfo[ci];
                    const unsigned s = packed >> 10, l = (packed >> 3) & 127u, n = packed & 7u;
                    const unsigned long long key =
                        ((unsigned long long)fmap(logit) << 32) |
                        (unsigned long long)(0xFFFFFFFFu - s);
                    atomicMax(&g_argmax[l * 8 + n], key);
                }
            }
        }
    }
}

// ---------------- K6: gather + lazy v_proj + Wo + residual + LayerNorm ----------------
__global__ __launch_bounds__(256) void finalize_kernel(
    const float* __restrict__ tgt,   const float* __restrict__ memory,
    const float* __restrict__ pos,
    const float* __restrict__ Wp,    const float* __restrict__ bp,
    const float* __restrict__ Wv,    const float* __restrict__ bv,
    const float* __restrict__ Wo,    const float* __restrict__ bo,
    const float* __restrict__ gamma, const float* __restrict__ beta,
    float* __restrict__ out)
{
    __shared__ float a[256];
    __shared__ float tmp[256];
    __shared__ float red[8];
    __shared__ int   s_sel;
    __shared__ float mu_s, var_s;

    const int t    = threadIdx.x;
    const int pair = blockIdx.x;           // = l*8 + n
    const int lane = t & 31, wid = t >> 5;

    if (t == 0) {
        const unsigned long long key = g_argmax[pair];
        s_sel = (int)(0xFFFFFFFFu - (unsigned)(key & 0xFFFFFFFFull));
    }
    __syncthreads();

    const int n    = pair & 7;
    const int rowk = s_sel * 8 + n;
    a[t] = memory[(size_t)rowk * 256 + t] + pos[(size_t)rowk * 256 + t];
    __syncthreads();

    float acc = bp[t];
    {
        const float4* w4 = (const float4*)&Wp[(size_t)t * 256];
#pragma unroll 8
        for (int k = 0; k < 64; ++k) {
            const float4 w = w4[k];
            acc += a[k * 4 + 0] * w.x + a[k * 4 + 1] * w.y
                 + a[k * 4 + 2] * w.z + a[k * 4 + 3] * w.w;
        }
    }
    tmp[t] = acc;
    __syncthreads();

    acc = bv[t];
    {
        const float4* w4 = (const float4*)&Wv[(size_t)t * 256];
#pragma unroll 8
        for (int k = 0; k < 64; ++k) {
            const float4 w = w4[k];
            acc += tmp[k * 4 + 0] * w.x + tmp[k * 4 + 1] * w.y
                 + tmp[k * 4 + 2] * w.z + tmp[k * 4 + 3] * w.w;
        }
    }
    a[t] = acc;
    __syncthreads();

    acc = bo[t];
    {
        const float4* w4 = (const float4*)&Wo[(size_t)t * 256];
#pragma unroll 8
        for (int k = 0; k < 64; ++k) {
            const float4 w = w4[k];
            acc += a[k * 4 + 0] * w.x + a[k * 4 + 1] * w.y
                 + a[k * 4 + 2] * w.z + a[k * 4 + 3] * w.w;
        }
    }
    const float x = tgt[(size_t)pair * 256 + t] + acc;

    float s = x;
#pragma unroll
    for (int off = 16; off > 0; off >>= 1) s += __shfl_xor_sync(0xffffffffu, s, off);
    if (lane == 0) red[wid] = s;
    __syncthreads();
    if (t == 0) {
        float tot = 0.f;
#pragma unroll
        for (int i = 0; i < 8; ++i) tot += red[i];
        mu_s = tot * (1.0f / 256.0f);
    }
    __syncthreads();
    const float mu = mu_s;
    const float d  = x - mu;
    float s2 = d * d;
#pragma unroll
    for (int off = 16; off > 0; off >>= 1) s2 += __shfl_xor_sync(0xffffffffu, s2, off);
    __syncthreads();
    if (lane == 0) red[wid] = s2;
    __syncthreads();
    if (t == 0) {
        float tot = 0.f;
#pragma unroll
        for (int i = 0; i < 8; ++i) tot += red[i];
        var_s = tot * (1.0f / 256.0f);
    }
    __syncthreads();

    const float rstd = rsqrtf(var_s + 1e-5f);
    out[(size_t)pair * 256 + t] = d * rstd * gamma[t] + beta[t];
}

// ---------------- launch ----------------
extern "C" void kernel_launch(void* const* d_in, const int* in_sizes, int n_in,
                              void* d_out, int out_size)
{
    const float* tgt       = (const float*)d_in[0];
    const float* memory    = (const float*)d_in[1];
    const float* pos       = (const float*)d_in[2];
    const float* query_pos = (const float*)d_in[3];
    const float* Wq        = (const float*)d_in[4];
    const float* bq        = (const float*)d_in[5];
    const float* Wp        = (const float*)d_in[6];
    const float* bp        = (const float*)d_in[7];
    const float* Wv        = (const float*)d_in[8];
    const float* bv        = (const float*)d_in[9];
    const float* Wo        = (const float*)d_in[10];
    const float* bo        = (const float*)d_in[11];
    const float* gamma     = (const float*)d_in[12];
    const float* beta      = (const float*)d_in[13];
    float* out             = (float*)d_out;

    init_kernel<<<4, 256>>>();
    wpconv_kernel<<<256, 256>>>(Wp);
    qproj_kernel<<<LN_ROWS / 8, 256>>>(tgt, query_pos, Wq, bq);
    kp_gemm_kernel<<<SN_ROWS / 64, 256>>>(memory, pos, bp);
    logits_pref_kernel<<<dim3(S_P / 128, N_B), 256>>>();
    collect_kernel<<<2048, 256>>>();
    rescore_kernel<<<1024, 256>>>(memory, pos, Wp, bp);
    finalize_kernel<<<LN_ROWS, 256>>>(tgt, memory, pos, Wp, bp, Wv, bv, Wo, bo,
                                      gamma, beta, out);
}

// round 6
// speedup vs baseline: 1.6010x; 1.0785x over previous
#include <cuda_runtime.h>
#include <cuda_bf16.h>
#include <cstdint>

// Problem constants
#define L_Q  128
#define N_B  8
#define S_P  16384
#define C_D  256
#define SN_ROWS (S_P * N_B)   // 131072
#define LN_ROWS (L_Q * N_B)   // 1024
#define MARGIN  0.30f
#define CAND_CAP (1u << 20)
#define POOL_CAP (1u << 22)

// ---------------- scratch ----------------
__device__ float          g_qproj[LN_ROWS * C_D];            // exact fp32 q_proj [l*8+n][c]
__device__ __nv_bfloat16  g_qb[LN_ROWS * C_D];               // bf16 q_proj [n][l][c]
__device__ __nv_bfloat16  g_wpb[C_D * C_D];                  // bf16 Wp
__device__ __nv_bfloat16  g_kn[(size_t)SN_ROWS * C_D];       // bf16 normalized k_proj [n][s][c]
__device__ uint2          g_pool[POOL_CAP];                  // {packed, logit_bits}
__device__ unsigned       g_npool;
__device__ unsigned       g_amax[LN_ROWS];                   // mapped-float global approx max
__device__ unsigned       g_cand[CAND_CAP];                  // packed (s<<10)|(l<<3)|n
__device__ unsigned       g_ncand;
__device__ unsigned long long g_argmax[LN_ROWS];             // packed (mapped_exact<<32)|~s

// ---------------- helpers ----------------
static __device__ __forceinline__ unsigned fmap(float x) {
    unsigned m = __float_as_uint(x);
    return (m & 0x80000000u) ? ~m : (m | 0x80000000u);
}
static __device__ __forceinline__ float funmap(unsigned u) {
    return __uint_as_float((u & 0x80000000u) ? (u ^ 0x80000000u) : ~u);
}
static __device__ __forceinline__ void mma_bf16(float c[4], const unsigned a[4],
                                                unsigned b0, unsigned b1) {
    asm volatile("mma.sync.aligned.m16n8k16.row.col.f32.bf16.bf16.f32 "
                 "{%0,%1,%2,%3}, {%4,%5,%6,%7}, {%8,%9}, {%0,%1,%2,%3};"
                 : "+f"(c[0]), "+f"(c[1]), "+f"(c[2]), "+f"(c[3])
                 : "r"(a[0]), "r"(a[1]), "r"(a[2]), "r"(a[3]), "r"(b0), "r"(b1));
}
static __device__ __forceinline__ void cp16(void* smem_dst, const void* gsrc) {
    unsigned d = (unsigned)__cvta_generic_to_shared(smem_dst);
    asm volatile("cp.async.cg.shared.global [%0], [%1], 16;\n" :: "r"(d), "l"(gsrc));
}
static __device__ __forceinline__ void cp_commit() {
    asm volatile("cp.async.commit_group;\n" ::: "memory");
}
static __device__ __forceinline__ void cp_wait1() {
    asm volatile("cp.async.wait_group 1;\n" ::: "memory");
}
static __device__ __forceinline__ void cp_wait0() {
    asm volatile("cp.async.wait_group 0;\n" ::: "memory");
}
static __device__ __forceinline__ unsigned pkbf(float x, float y) {
    __nv_bfloat162 h = __floats2bfloat162_rn(x, y);
    return *(unsigned*)&h;
}

// ---------------- K0: init ----------------
__global__ void init_kernel() {
    int i = blockIdx.x * blockDim.x + threadIdx.x;
    if (i < LN_ROWS) { g_amax[i] = 0u; g_argmax[i] = 0ull; }
    if (i == 0) { g_ncand = 0u; g_npool = 0u; }
}

// ---------------- K0b: Wp -> bf16 ----------------
__global__ void wpconv_kernel(const float* __restrict__ Wp) {
    int i = blockIdx.x * blockDim.x + threadIdx.x;   // 65536
    g_wpb[i] = __float2bfloat16(Wp[i]);
}

// ---------------- K1: exact fp32 q_proj (+ bf16 copy, [n][l][c]) ----------------
__global__ __launch_bounds__(256) void qproj_kernel(
    const float* __restrict__ tgt, const float* __restrict__ qpos,
    const float* __restrict__ Wq,  const float* __restrict__ bq)
{
    __shared__ float a_s[8][256];
    const int t  = threadIdx.x;
    const int r0 = blockIdx.x * 8;
#pragma unroll
    for (int r = 0; r < 8; ++r)
        a_s[r][t] = tgt[(size_t)(r0 + r) * 256 + t] + qpos[(size_t)(r0 + r) * 256 + t];
    __syncthreads();
    float acc[8];
#pragma unroll
    for (int r = 0; r < 8; ++r) acc[r] = bq[t];
    const float4* w4 = (const float4*)&Wq[(size_t)t * 256];
#pragma unroll 4
    for (int k4 = 0; k4 < 64; ++k4) {
        const float4 w = w4[k4];
#pragma unroll
        for (int r = 0; r < 8; ++r) {
            const float4 a = *(const float4*)&a_s[r][k4 * 4];
            acc[r] += a.x * w.x + a.y * w.y + a.z * w.z + a.w * w.w;
        }
    }
#pragma unroll
    for (int r = 0; r < 8; ++r) {
        const int row = r0 + r;            // = l*8 + n
        const int l = row >> 3, n = row & 7;
        g_qproj[(size_t)row * 256 + t] = acc[r];
        g_qb[((size_t)n * L_Q + l) * 256 + t] = __float2bfloat16(acc[r]);
    }
}

// ---------------- K2: bf16 MMA k_proj + L2-normalize -> g_kn[n][s][c] ----------------
// CTA tile: 64 rows (s*8+n flattened) x 256 cols, K in chunks of 32, cp.async 2-stage.
// Dynamic smem layout (bytes):
//   Am fp32 [2][64][44] : 0      .. 22528
//   Ap fp32 [2][64][44] : 22528  .. 45056
//   Bs bf16 [2][256][40]: 45056  .. 86016
//   bsm fp32 [256]      : 86016  .. 87040
//   rowss fp32 [64]     : 87040  .. 87296
#define KP_SMEM 87296
__global__ __launch_bounds__(256, 2) void kp_gemm_kernel(
    const float* __restrict__ mem, const float* __restrict__ pos,
    const float* __restrict__ bp)
{
    extern __shared__ char sm_raw[];
    float*         Am    = (float*)sm_raw;
    float*         Ap    = (float*)(sm_raw + 22528);
    __nv_bfloat16* Bs    = (__nv_bfloat16*)(sm_raw + 45056);
    float*         bsm   = (float*)(sm_raw + 86016);
    float*         rowss = (float*)(sm_raw + 87040);

    const int t = threadIdx.x, lane = t & 31, wid = t >> 5;
    const int g = lane >> 2, tid4 = lane & 3;
    const int wm = wid & 1, wn = wid >> 1;
    const int row0 = blockIdx.x * 64;

    if (t < 64) rowss[t] = 0.f;
    bsm[t] = bp[t];

    float acc[2][8][4];
#pragma unroll
    for (int mf = 0; mf < 2; ++mf)
#pragma unroll
        for (int nf = 0; nf < 8; ++nf)
#pragma unroll
            for (int c = 0; c < 4; ++c) acc[mf][nf][c] = 0.f;

#define KP_ISSUE(st, kt)                                                          \
    {                                                                             \
        const int _st = (st), _kt = (kt);                                         \
        _Pragma("unroll")                                                         \
        for (int i = 0; i < 2; ++i) {                                             \
            const int q = t + i * 256, r = q >> 3, c = q & 7;                     \
            cp16(&Am[_st * 2816 + r * 44 + c * 4],                                \
                 &mem[(size_t)(row0 + r) * 256 + _kt + c * 4]);                   \
            cp16(&Ap[_st * 2816 + r * 44 + c * 4],                                \
                 &pos[(size_t)(row0 + r) * 256 + _kt + c * 4]);                   \
        }                                                                         \
        _Pragma("unroll")                                                         \
        for (int i = 0; i < 4; ++i) {                                             \
            const int q = t + i * 256, r = q >> 2, c = q & 3;                     \
            cp16(&Bs[_st * 10240 + r * 40 + c * 8],                               \
                 &g_wpb[(size_t)r * 256 + _kt + c * 8]);                          \
        }                                                                         \
    }

    KP_ISSUE(0, 0);
    cp_commit();

    for (int it = 0; it < 8; ++it) {
        if (it < 7) { KP_ISSUE((it + 1) & 1, (it + 1) * 32); cp_commit(); cp_wait1(); }
        else        { cp_wait0(); }
        __syncthreads();
        const int st = it & 1;
        const float*         AmS = &Am[st * 2816];
        const float*         ApS = &Ap[st * 2816];
        const __nv_bfloat16* BsS = &Bs[st * 10240];
#pragma unroll
        for (int k2 = 0; k2 < 2; ++k2) {
            unsigned a[2][4];
#pragma unroll
            for (int mf = 0; mf < 2; ++mf) {
                const int rb = wm * 32 + mf * 16;
#pragma unroll
                for (int half = 0; half < 2; ++half) {
                    const int kk = k2 * 16 + half * 8 + 2 * tid4;
                    const float2 m0 = *(const float2*)&AmS[(rb + g) * 44 + kk];
                    const float2 p0 = *(const float2*)&ApS[(rb + g) * 44 + kk];
                    const float2 m1 = *(const float2*)&AmS[(rb + g + 8) * 44 + kk];
                    const float2 p1 = *(const float2*)&ApS[(rb + g + 8) * 44 + kk];
                    a[mf][half * 2 + 0] = pkbf(m0.x + p0.x, m0.y + p0.y);
                    a[mf][half * 2 + 1] = pkbf(m1.x + p1.x, m1.y + p1.y);
                }
            }
#pragma unroll
            for (int nf = 0; nf < 8; ++nf) {
                const int c = wn * 64 + nf * 8 + g;
                const unsigned b0 = *(const unsigned*)&BsS[c * 40 + k2 * 16 + 2 * tid4];
                const unsigned b1 = *(const unsigned*)&BsS[c * 40 + k2 * 16 + 8 + 2 * tid4];
                mma_bf16(acc[0][nf], a[0], b0, b1);
                mma_bf16(acc[1][nf], a[1], b0, b1);
            }
        }
        __syncthreads();
    }

    // epilogue: per-row sum of squares (bias added)
#pragma unroll
    for (int mf = 0; mf < 2; ++mf) {
        float ss0 = 0.f, ss1 = 0.f;
#pragma unroll
        for (int nf = 0; nf < 8; ++nf) {
            const int c = wn * 64 + nf * 8 + 2 * tid4;
            const float b0v = bsm[c], b1v = bsm[c + 1];
            const float v00 = acc[mf][nf][0] + b0v, v01 = acc[mf][nf][1] + b1v;
            const float v10 = acc[mf][nf][2] + b0v, v11 = acc[mf][nf][3] + b1v;
            ss0 += v00 * v00 + v01 * v01;
            ss1 += v10 * v10 + v11 * v11;
        }
        ss0 += __shfl_xor_sync(0xffffffffu, ss0, 1);
        ss0 += __shfl_xor_sync(0xffffffffu, ss0, 2);
        ss1 += __shfl_xor_sync(0xffffffffu, ss1, 1);
        ss1 += __shfl_xor_sync(0xffffffffu, ss1, 2);
        if (tid4 == 0) {
            atomicAdd(&rowss[wm * 32 + mf * 16 + g], ss0);
            atomicAdd(&rowss[wm * 32 + mf * 16 + g + 8], ss1);
        }
    }
    __syncthreads();
#pragma unroll
    for (int mf = 0; mf < 2; ++mf) {
        const int r0l = wm * 32 + mf * 16 + g, r1l = r0l + 8;
        const float inv0 = 1.f / fmaxf(sqrtf(rowss[r0l]), 1e-12f);
        const float inv1 = 1.f / fmaxf(sqrtf(rowss[r1l]), 1e-12f);
        const int sn0 = row0 + r0l, sn1 = row0 + r1l;
        __nv_bfloat16* o0 = &g_kn[((size_t)(sn0 & 7) * S_P + (sn0 >> 3)) * 256];
        __nv_bfloat16* o1 = &g_kn[((size_t)(sn1 & 7) * S_P + (sn1 >> 3)) * 256];
#pragma unroll
        for (int nf = 0; nf < 8; ++nf) {
            const int c = wn * 64 + nf * 8 + 2 * tid4;
            const float b0v = bsm[c], b1v = bsm[c + 1];
            *(__nv_bfloat162*)&o0[c] =
                __floats2bfloat162_rn((acc[mf][nf][0] + b0v) * inv0,
                                      (acc[mf][nf][1] + b1v) * inv0);
            *(__nv_bfloat162*)&o1[c] =
                __floats2bfloat162_rn((acc[mf][nf][2] + b0v) * inv1,
                                      (acc[mf][nf][3] + b1v) * inv1);
        }
    }
}

// ---------------- K3: bf16 MMA approx logits + fused candidate collection ----------------
// CTA: (s-tile 128, n). M=s(128): wm=wid&3; N=l(128): wn=wid>>2. cp.async 2-stage.
__global__ __launch_bounds__(256, 2) void logits_pref_kernel()
{
    __shared__ __nv_bfloat16 As[2 * 128 * 40];   // kn rows (pad 40)
    __shared__ __nv_bfloat16 Bs[2 * 128 * 40];   // q rows
    __shared__ unsigned amax_s[128];
    __shared__ float    thr_s[128];
    __shared__ unsigned wtot[8], woff[8];
    __shared__ unsigned base_s;

    const int t = threadIdx.x, lane = t & 31, wid = t >> 5;
    const int g = lane >> 2, tid4 = lane & 3;
    const int wm = wid & 3, wn = wid >> 2;
    const int s0 = blockIdx.x * 128;
    const int n  = blockIdx.y;

    if (t < 128) amax_s[t] = 0u;

    float acc[2][8][4];
#pragma unroll
    for (int mf = 0; mf < 2; ++mf)
#pragma unroll
        for (int nf = 0; nf < 8; ++nf)
#pragma unroll
            for (int c = 0; c < 4; ++c) acc[mf][nf][c] = 0.f;

#define LG_ISSUE(st, kt)                                                          \
    {                                                                             \
        const int _st = (st), _kt = (kt);                                         \
        _Pragma("unroll")                                                         \
        for (int i = 0; i < 2; ++i) {                                             \
            const int q = t + i * 256, r = q >> 2, c = q & 3;                     \
            cp16(&As[_st * 5120 + r * 40 + c * 8],                                \
                 &g_kn[((size_t)n * S_P + s0 + r) * 256 + _kt + c * 8]);          \
            cp16(&Bs[_st * 5120 + r * 40 + c * 8],                                \
                 &g_qb[((size_t)n * L_Q + r) * 256 + _kt + c * 8]);               \
        }                                                                         \
    }

    LG_ISSUE(0, 0);
    cp_commit();

    for (int it = 0; it < 8; ++it) {
        if (it < 7) { LG_ISSUE((it + 1) & 1, (it + 1) * 32); cp_commit(); cp_wait1(); }
        else        { cp_wait0(); }
        __syncthreads();
        const int st = it & 1;
        const __nv_bfloat16* AsS = &As[st * 5120];
        const __nv_bfloat16* BsS = &Bs[st * 5120];
#pragma unroll
        for (int k2 = 0; k2 < 2; ++k2) {
            unsigned a[2][4];
#pragma unroll
            for (int mf = 0; mf < 2; ++mf) {
                const int r = wm * 32 + mf * 16;
                a[mf][0] = *(const unsigned*)&AsS[(r + g)     * 40 + k2 * 16 + 2 * tid4];
                a[mf][1] = *(const unsigned*)&AsS[(r + g + 8) * 40 + k2 * 16 + 2 * tid4];
                a[mf][2] = *(const unsigned*)&AsS[(r + g)     * 40 + k2 * 16 + 8 + 2 * tid4];
                a[mf][3] = *(const unsigned*)&AsS[(r + g + 8) * 40 + k2 * 16 + 8 + 2 * tid4];
            }
#pragma unroll
            for (int nf = 0; nf < 8; ++nf) {
                const int c = wn * 64 + nf * 8 + g;
                const unsigned b0 = *(const unsigned*)&BsS[c * 40 + k2 * 16 + 2 * tid4];
                const unsigned b1 = *(const unsigned*)&BsS[c * 40 + k2 * 16 + 8 + 2 * tid4];
                mma_bf16(acc[0][nf], a[0], b0, b1);
                mma_bf16(acc[1][nf], a[1], b0, b1);
            }
        }
        __syncthreads();
    }

    // --- CTA-local per-l max ---
#pragma unroll
    for (int nf = 0; nf < 8; ++nf) {
        float m0 = fmaxf(fmaxf(acc[0][nf][0], acc[0][nf][2]),
                         fmaxf(acc[1][nf][0], acc[1][nf][2]));
        float m1 = fmaxf(fmaxf(acc[0][nf][1], acc[0][nf][3]),
                         fmaxf(acc[1][nf][1], acc[1][nf][3]));
#pragma unroll
        for (int off = 4; off < 32; off <<= 1) {
            m0 = fmaxf(m0, __shfl_xor_sync(0xffffffffu, m0, off));
            m1 = fmaxf(m1, __shfl_xor_sync(0xffffffffu, m1, off));
        }
        if (lane < 4) {
            const int lc = wn * 64 + nf * 8 + 2 * lane;
            atomicMax(&amax_s[lc],     fmap(m0));
            atomicMax(&amax_s[lc + 1], fmap(m1));
        }
    }
    __syncthreads();
    if (t < 128) {
        atomicMax(&g_amax[t * 8 + n], amax_s[t]);
        thr_s[t] = funmap(amax_s[t]) - MARGIN;
    }
    __syncthreads();

    // --- count survivors (within MARGIN of CTA-local max) ---
    int cnt = 0;
#pragma unroll
    for (int mf = 0; mf < 2; ++mf)
#pragma unroll
        for (int nf = 0; nf < 8; ++nf)
#pragma unroll
            for (int c = 0; c < 4; ++c) {
                const int lc = wn * 64 + nf * 8 + 2 * tid4 + (c & 1);
                if (acc[mf][nf][c] >= thr_s[lc]) ++cnt;
            }

    // CTA scan -> one atomicAdd for pool base
    int incl = cnt;
#pragma unroll
    for (int off = 1; off < 32; off <<= 1) {
        const int v = __shfl_up_sync(0xffffffffu, incl, off);
        if (lane >= off) incl += v;
    }
    if (lane == 31) wtot[wid] = (unsigned)incl;
    __syncthreads();
    if (t == 0) {
        unsigned tot = 0;
#pragma unroll
        for (int w = 0; w < 8; ++w) { woff[w] = tot; tot += wtot[w]; }
        base_s = atomicAdd(&g_npool, tot);
    }
    __syncthreads();
    unsigned p = base_s + woff[wid] + (unsigned)(incl - cnt);

#pragma unroll
    for (int mf = 0; mf < 2; ++mf)
#pragma unroll
        for (int nf = 0; nf < 8; ++nf)
#pragma unroll
            for (int c = 0; c < 4; ++c) {
                const int lc = wn * 64 + nf * 8 + 2 * tid4 + (c & 1);
                const float v = acc[mf][nf][c];
                if (v >= thr_s[lc]) {
                    const int sr = s0 + wm * 32 + mf * 16 + g + ((c >= 2) ? 8 : 0);
                    if (p < POOL_CAP)
                        g_pool[p] = make_uint2(((unsigned)sr << 10) |
                                               ((unsigned)lc << 3) | (unsigned)n,
                                               __float_as_uint(v));
                    ++p;
                }
            }
}

// ---------------- K4: filter pool against global approx max ----------------
__global__ __launch_bounds__(256) void filter_kernel()
{
    __shared__ float thr_s[LN_ROWS];
    const int t = threadIdx.x;
    for (int i = t; i < LN_ROWS; i += 256) thr_s[i] = funmap(g_amax[i]) - MARGIN;
    __syncthreads();
    const unsigned np = min(g_npool, (unsigned)POOL_CAP);
    for (unsigned idx = blockIdx.x * 256 + t; idx < np; idx += gridDim.x * 256) {
        const uint2 e = g_pool[idx];
        const unsigned l = (e.x >> 3) & 127u, n = e.x & 7u;
        if (__uint_as_float(e.y) >= thr_s[l * 8 + n]) {
            const unsigned pp = atomicAdd(&g_ncand, 1u);
            if (pp < CAND_CAP) g_cand[pp] = e.x;
        }
    }
}

// ---------------- K5: exact fp32 rescore of candidates ----------------
__global__ __launch_bounds__(256) void rescore_kernel(
    const float* __restrict__ mem, const float* __restrict__ pos,
    const float* __restrict__ Wp,  const float* __restrict__ bp)
{
    __shared__ float a_s[8][256];
    __shared__ float q_s[8][256];
    __shared__ unsigned cinfo[8];
    __shared__ float rss[8], rqd[8];
    __shared__ unsigned count_s;

    const int t = threadIdx.x, lane = t & 31, wid = t >> 5;
    if (t == 0) count_s = min(g_ncand, (unsigned)CAND_CAP);
    __syncthreads();
    const unsigned count = count_s;

    for (unsigned chunk = blockIdx.x; chunk * 8u < count; chunk += gridDim.x) {
        __syncthreads();
#pragma unroll
        for (int ci = 0; ci < 8; ++ci) {
            const unsigned c = chunk * 8u + ci;
            const unsigned packed = g_cand[(c < count) ? c : chunk * 8u];
            const unsigned s = packed >> 10, n = packed & 7u;
            a_s[ci][t] = mem[((size_t)s * 8 + n) * 256 + t]
                       + pos[((size_t)s * 8 + n) * 256 + t];
            const unsigned l = (packed >> 3) & 127u;
            q_s[ci][t] = g_qproj[((size_t)l * 8 + n) * 256 + t];
            if (t == ci) cinfo[ci] = packed;
        }
        __syncthreads();

        float acc[8];
#pragma unroll
        for (int ci = 0; ci < 8; ++ci) acc[ci] = bp[t];
        const float4* w4 = (const float4*)&Wp[(size_t)t * 256];
#pragma unroll 4
        for (int k4 = 0; k4 < 64; ++k4) {
            const float4 w = w4[k4];
#pragma unroll
            for (int ci = 0; ci < 8; ++ci) {
                const float4 a = *(const float4*)&a_s[ci][k4 * 4];
                acc[ci] += a.x * w.x + a.y * w.y + a.z * w.z + a.w * w.w;
            }
        }

        for (int ci = 0; ci < 8; ++ci) {
            const float kp = acc[ci];
            float ss = kp * kp;
            float qd = q_s[ci][t] * kp;
#pragma unroll
            for (int off = 16; off > 0; off >>= 1) {
                ss += __shfl_xor_sync(0xffffffffu, ss, off);
                qd += __shfl_xor_sync(0xffffffffu, qd, off);
            }
            __syncthreads();
            if (lane == 0) { rss[wid] = ss; rqd[wid] = qd; }
            __syncthreads();
            if (t == 0) {
                const unsigned c = chunk * 8u + ci;
                if (c < count) {
                    float S = 0.f, Q = 0.f;
#pragma unroll
                    for (int w = 0; w < 8; ++w) { S += rss[w]; Q += rqd[w]; }
                    const float logit = Q / fmaxf(sqrtf(S), 1e-12f);
                    const unsigned packed = cinfo[ci];
                    const unsigned s = packed >> 10, l = (packed >> 3) & 127u, nn = packed & 7u;
                    const unsigned long long key =
                        ((unsigned long long)fmap(logit) << 32) |
                        (unsigned long long)(0xFFFFFFFFu - s);
                    atomicMax(&g_argmax[l * 8 + nn], key);
                }
            }
        }
    }
}

// ---------------- K6: gather + lazy v_proj + Wo + residual + LayerNorm ----------------
__global__ __launch_bounds__(256) void finalize_kernel(
    const float* __restrict__ tgt,   const float* __restrict__ memory,
    const float* __restrict__ pos,
    const float* __restrict__ Wp,    const float* __restrict__ bp,
    const float* __restrict__ Wv,    const float* __restrict__ bv,
    const float* __restrict__ Wo,    const float* __restrict__ bo,
    const float* __restrict__ gamma, const float* __restrict__ beta,
    float* __restrict__ out)
{
    __shared__ float a[256];
    __shared__ float tmp[256];
    __shared__ float red[8];
    __shared__ int   s_sel;
    __shared__ float mu_s, var_s;

    const int t    = threadIdx.x;
    const int pair = blockIdx.x;           // = l*8 + n
    const int lane = t & 31, wid = t >> 5;

    if (t == 0) {
        const unsigned long long key = g_argmax[pair];
        s_sel = (int)(0xFFFFFFFFu - (unsigned)(key & 0xFFFFFFFFull));
    }
    __syncthreads();

    const int n    = pair & 7;
    const int rowk = s_sel * 8 + n;
    a[t] = memory[(size_t)rowk * 256 + t] + pos[(size_t)rowk * 256 + t];
    __syncthreads();

    float acc = bp[t];
    {
        const float4* w4 = (const float4*)&Wp[(size_t)t * 256];
#pragma unroll 8
        for (int k = 0; k < 64; ++k) {
            const float4 w = w4[k];
            acc += a[k * 4 + 0] * w.x + a[k * 4 + 1] * w.y
                 + a[k * 4 + 2] * w.z + a[k * 4 + 3] * w.w;
        }
    }
    tmp[t] = acc;
    __syncthreads();

    acc = bv[t];
    {
        const float4* w4 = (const float4*)&Wv[(size_t)t * 256];
#pragma unroll 8
        for (int k = 0; k < 64; ++k) {
            const float4 w = w4[k];
            acc += tmp[k * 4 + 0] * w.x + tmp[k * 4 + 1] * w.y
                 + tmp[k * 4 + 2] * w.z + tmp[k * 4 + 3] * w.w;
        }
    }
    a[t] = acc;
    __syncthreads();

    acc = bo[t];
    {
        const float4* w4 = (const float4*)&Wo[(size_t)t * 256];
#pragma unroll 8
        for (int k = 0; k < 64; ++k) {
            const float4 w = w4[k];
            acc += a[k * 4 + 0] * w.x + a[k * 4 + 1] * w.y
                 + a[k * 4 + 2] * w.z + a[k * 4 + 3] * w.w;
        }
    }
    const float x = tgt[(size_t)pair * 256 + t] + acc;

    float s = x;
#pragma unroll
    for (int off = 16; off > 0; off >>= 1) s += __shfl_xor_sync(0xffffffffu, s, off);
    if (lane == 0) red[wid] = s;
    __syncthreads();
    if (t == 0) {
        float tot = 0.f;
#pragma unroll
        for (int i = 0; i < 8; ++i) tot += red[i];
        mu_s = tot * (1.0f / 256.0f);
    }
    __syncthreads();
    const float mu = mu_s;
    const float d  = x - mu;
    float s2 = d * d;
#pragma unroll
    for (int off = 16; off > 0; off >>= 1) s2 += __shfl_xor_sync(0xffffffffu, s2, off);
    __syncthreads();
    if (lane == 0) red[wid] = s2;
    __syncthreads();
    if (t == 0) {
        float tot = 0.f;
#pragma unroll
        for (int i = 0; i < 8; ++i) tot += red[i];
        var_s = tot * (1.0f / 256.0f);
    }
    __syncthreads();

    const float rstd = rsqrtf(var_s + 1e-5f);
    out[(size_t)pair * 256 + t] = d * rstd * gamma[t] + beta[t];
}

// ---------------- launch ----------------
extern "C" void kernel_launch(void* const* d_in, const int* in_sizes, int n_in,
                              void* d_out, int out_size)
{
    const float* tgt       = (const float*)d_in[0];
    const float* memory    = (const float*)d_in[1];
    const float* pos       = (const float*)d_in[2];
    const float* query_pos = (const float*)d_in[3];
    const float* Wq        = (const float*)d_in[4];
    const float* bq        = (const float*)d_in[5];
    const float* Wp        = (const float*)d_in[6];
    const float* bp        = (const float*)d_in[7];
    const float* Wv        = (const float*)d_in[8];
    const float* bv        = (const float*)d_in[9];
    const float* Wo        = (const float*)d_in[10];
    const float* bo        = (const float*)d_in[11];
    const float* gamma     = (const float*)d_in[12];
    const float* beta      = (const float*)d_in[13];
    float* out             = (float*)d_out;

    cudaFuncSetAttribute(kp_gemm_kernel,
                         cudaFuncAttributeMaxDynamicSharedMemorySize, KP_SMEM);

    init_kernel<<<4, 256>>>();
    wpconv_kernel<<<256, 256>>>(Wp);
    qproj_kernel<<<LN_ROWS / 8, 256>>>(tgt, query_pos, Wq, bq);
    kp_gemm_kernel<<<SN_ROWS / 64, 256, KP_SMEM>>>(memory, pos, bp);
    logits_pref_kernel<<<dim3(S_P / 128, N_B), 256>>>();
    filter_kernel<<<512, 256>>>();
    rescore_kernel<<<512, 256>>>(memory, pos, Wp, bp);
    finalize_kernel<<<LN_ROWS, 256>>>(tgt, memory, pos, Wp, bp, Wv, bv, Wo, bo,
                                      gamma, beta, out);
}

// round 7
// speedup vs baseline: 1.7178x; 1.0729x over previous
#include <cuda_runtime.h>
#include <cuda_bf16.h>
#include <cstdint>

// Problem constants
#define L_Q  128
#define N_B  8
#define S_P  16384
#define C_D  256
#define SN_ROWS (S_P * N_B)   // 131072
#define LN_ROWS (L_Q * N_B)   // 1024
#define MARGIN  0.30f
#define CAND_CAP (1u << 20)
#define POOL_CAP (1u << 22)

// ---------------- scratch ----------------
__device__ float          g_qproj[LN_ROWS * C_D];            // exact fp32 q_proj [l*8+n][c]
__device__ __nv_bfloat16  g_qb[LN_ROWS * C_D];               // bf16 q_proj [n][l][c]
__device__ __nv_bfloat16  g_wpb[C_D * C_D];                  // bf16 Wp
__device__ uint2          g_pool[POOL_CAP];                  // {packed, logit_bits}
__device__ unsigned       g_npool;
__device__ unsigned       g_amax[LN_ROWS];                   // mapped-float global approx max
__device__ unsigned       g_cand[CAND_CAP];                  // packed (s<<10)|(l<<3)|n
__device__ unsigned       g_ncand;
__device__ unsigned long long g_argmax[LN_ROWS];             // packed (mapped_exact<<32)|~s

// ---------------- helpers ----------------
static __device__ __forceinline__ unsigned fmap(float x) {
    unsigned m = __float_as_uint(x);
    return (m & 0x80000000u) ? ~m : (m | 0x80000000u);
}
static __device__ __forceinline__ float funmap(unsigned u) {
    return __uint_as_float((u & 0x80000000u) ? (u ^ 0x80000000u) : ~u);
}
static __device__ __forceinline__ void mma_bf16(float c[4], const unsigned a[4],
                                                unsigned b0, unsigned b1) {
    asm volatile("mma.sync.aligned.m16n8k16.row.col.f32.bf16.bf16.f32 "
                 "{%0,%1,%2,%3}, {%4,%5,%6,%7}, {%8,%9}, {%0,%1,%2,%3};"
                 : "+f"(c[0]), "+f"(c[1]), "+f"(c[2]), "+f"(c[3])
                 : "r"(a[0]), "r"(a[1]), "r"(a[2]), "r"(a[3]), "r"(b0), "r"(b1));
}
static __device__ __forceinline__ void cp16(void* smem_dst, const void* gsrc) {
    unsigned d = (unsigned)__cvta_generic_to_shared(smem_dst);
    asm volatile("cp.async.cg.shared.global [%0], [%1], 16;\n" :: "r"(d), "l"(gsrc));
}
static __device__ __forceinline__ void cp_commit() {
    asm volatile("cp.async.commit_group;\n" ::: "memory");
}
static __device__ __forceinline__ void cp_wait1() {
    asm volatile("cp.async.wait_group 1;\n" ::: "memory");
}
static __device__ __forceinline__ void cp_wait0() {
    asm volatile("cp.async.wait_group 0;\n" ::: "memory");
}
static __device__ __forceinline__ unsigned pkbf(float x, float y) {
    __nv_bfloat162 h = __floats2bfloat162_rn(x, y);
    return *(unsigned*)&h;
}

// Swizzled byte offset inside a [rows][256 bf16] tile: 32 16B-units per 512B row;
// XOR of low-3 unit bits with (row&7) => conflict-free 8-row fragment access.
#define SWZB(row, unit) (((row) << 9) + ((((unit) ^ ((row) & 7))) << 4))

// ---------------- K0: init ----------------
__global__ void init_kernel() {
    int i = blockIdx.x * blockDim.x + threadIdx.x;
    if (i < LN_ROWS) { g_amax[i] = 0u; g_argmax[i] = 0ull; }
    if (i == 0) { g_ncand = 0u; g_npool = 0u; }
}

// ---------------- K0b: Wp -> bf16 ----------------
__global__ void wpconv_kernel(const float* __restrict__ Wp) {
    int i = blockIdx.x * blockDim.x + threadIdx.x;   // 65536
    g_wpb[i] = __float2bfloat16(Wp[i]);
}

// ---------------- K1: exact fp32 q_proj (+ bf16 copy, [n][l][c]) ----------------
__global__ __launch_bounds__(256) void qproj_kernel(
    const float* __restrict__ tgt, const float* __restrict__ qpos,
    const float* __restrict__ Wq,  const float* __restrict__ bq)
{
    __shared__ float a_s[8][256];
    const int t  = threadIdx.x;
    const int r0 = blockIdx.x * 8;
#pragma unroll
    for (int r = 0; r < 8; ++r)
        a_s[r][t] = tgt[(size_t)(r0 + r) * 256 + t] + qpos[(size_t)(r0 + r) * 256 + t];
    __syncthreads();
    float acc[8];
#pragma unroll
    for (int r = 0; r < 8; ++r) acc[r] = bq[t];
    const float4* w4 = (const float4*)&Wq[(size_t)t * 256];
#pragma unroll 4
    for (int k4 = 0; k4 < 64; ++k4) {
        const float4 w = w4[k4];
#pragma unroll
        for (int r = 0; r < 8; ++r) {
            const float4 a = *(const float4*)&a_s[r][k4 * 4];
            acc[r] += a.x * w.x + a.y * w.y + a.z * w.z + a.w * w.w;
        }
    }
#pragma unroll
    for (int r = 0; r < 8; ++r) {
        const int row = r0 + r;            // = l*8 + n
        const int l = row >> 3, n = row & 7;
        g_qproj[(size_t)row * 256 + t] = acc[r];
        g_qb[((size_t)n * L_Q + l) * 256 + t] = __float2bfloat16(acc[r]);
    }
}

// ---------------- K2: FUSED k_proj + normalize + logits + candidate collection ----
// CTA = (128 s-rows, batch n). grid (128, 8).
// Dynamic smem (196608 B):
//   AS [0,      65536): A = bf16(mem+pos), 128x256, swizzled
//   WQ [65536, 131072): phase1 = Wp col-block double buffer (2 x 32KB, 64x256 each)
//                       phase2 = q tile 128x256 bf16, swizzled
//   KP [131072,196608): kp tile 128x256 bf16 (bias added, unnormalized), swizzled
#define FU_SMEM 196608
__global__ __launch_bounds__(256, 1) void fused_kernel(
    const float* __restrict__ mem, const float* __restrict__ pos,
    const float* __restrict__ bp)
{
    extern __shared__ char sm[];
    char* AS = sm;
    char* WQ = sm + 65536;
    char* KP = sm + 131072;
    __shared__ float    rowss[128];     // sum-sq -> later 1/norm
    __shared__ float    bsm[256];
    __shared__ unsigned amax_s[128];
    __shared__ float    thr_s[128];
    __shared__ unsigned wtot[8], woff[8], base_s;

    const int t = threadIdx.x, lane = t & 31, wid = t >> 5;
    const int g = lane >> 2, tid4 = lane & 3;
    const int s0 = blockIdx.x * 128;
    const int n  = blockIdx.y;

    if (t < 128) { rowss[t] = 0.f; amax_s[t] = 0u; }
    bsm[t] = bp[t];

#define WP_ISSUE(blk, buf)                                                        \
    {                                                                             \
        _Pragma("unroll")                                                         \
        for (int i = 0; i < 8; ++i) {                                             \
            const int id = t + i * 256, r = id >> 5, u = id & 31;                 \
            cp16(WQ + (buf) * 32768 + SWZB(r, u),                                 \
                 &g_wpb[((blk) * 64 + r) * 256 + u * 8]);                         \
        }                                                                         \
    }
#define Q_ISSUE_HALF(h)                                                           \
    {                                                                             \
        _Pragma("unroll")                                                         \
        for (int i = 0; i < 8; ++i) {                                             \
            const int id = t + i * 256, rq = (h) * 64 + (id >> 5), u = id & 31;   \
            cp16(WQ + SWZB(rq, u), &g_qb[((size_t)n * L_Q + rq) * 256 + u * 8]);  \
        }                                                                         \
    }

    WP_ISSUE(0, 0); cp_commit();

    // ---- A staging: bf16(mem+pos), swizzled (overlaps with Wp cp.async) ----
#pragma unroll
    for (int i = 0; i < 16; ++i) {
        const int id = t + i * 256, r = id >> 5, u = id & 31;
        const size_t base = ((size_t)(s0 + r) * 8 + n) * 256 + u * 8;
        const float4 m0 = *(const float4*)&mem[base];
        const float4 m1 = *(const float4*)&mem[base + 4];
        const float4 p0 = *(const float4*)&pos[base];
        const float4 p1 = *(const float4*)&pos[base + 4];
        uint4 v;
        v.x = pkbf(m0.x + p0.x, m0.y + p0.y);
        v.y = pkbf(m0.z + p0.z, m0.w + p0.w);
        v.z = pkbf(m1.x + p1.x, m1.y + p1.y);
        v.w = pkbf(m1.z + p1.z, m1.w + p1.w);
        *(uint4*)(AS + SWZB(r, u)) = v;
    }
    WP_ISSUE(1, 1); cp_commit();

    // ---- Phase 1: kp = A @ Wp^T (+bias), 4 col-blocks of 64 ----
    {
        const int wm = wid & 3, wn = wid & 4 ? 1 : 0;   // 4 s-groups x 2 j-groups
        for (int jblk = 0; jblk < 4; ++jblk) {
            cp_wait1();
            __syncthreads();
            const char* WB = WQ + (jblk & 1) * 32768;
            float acc[2][4][4];
#pragma unroll
            for (int mf = 0; mf < 2; ++mf)
#pragma unroll
                for (int nf = 0; nf < 4; ++nf)
#pragma unroll
                    for (int c = 0; c < 4; ++c) acc[mf][nf][c] = 0.f;
#pragma unroll
            for (int kk = 0; kk < 16; ++kk) {
                unsigned a[2][4];
#pragma unroll
                for (int mf = 0; mf < 2; ++mf) {
                    const int r0 = wm * 32 + mf * 16 + g;
                    a[mf][0] = *(const unsigned*)(AS + SWZB(r0,     2 * kk)     + tid4 * 4);
                    a[mf][1] = *(const unsigned*)(AS + SWZB(r0 + 8, 2 * kk)     + tid4 * 4);
                    a[mf][2] = *(const unsigned*)(AS + SWZB(r0,     2 * kk + 1) + tid4 * 4);
                    a[mf][3] = *(const unsigned*)(AS + SWZB(r0 + 8, 2 * kk + 1) + tid4 * 4);
                }
#pragma unroll
                for (int nf = 0; nf < 4; ++nf) {
                    const int c = wn * 32 + nf * 8 + g;
                    const unsigned b0 = *(const unsigned*)(WB + SWZB(c, 2 * kk)     + tid4 * 4);
                    const unsigned b1 = *(const unsigned*)(WB + SWZB(c, 2 * kk + 1) + tid4 * 4);
                    mma_bf16(acc[0][nf], a[0], b0, b1);
                    mma_bf16(acc[1][nf], a[1], b0, b1);
                }
            }
            // epilogue: +bias, sum-sq, store bf16 kp tile
#pragma unroll
            for (int mf = 0; mf < 2; ++mf) {
                const int r0 = wm * 32 + mf * 16 + g;
                float ss0 = 0.f, ss1 = 0.f;
#pragma unroll
                for (int nf = 0; nf < 4; ++nf) {
                    const int jc = jblk * 64 + wn * 32 + nf * 8 + 2 * tid4;
                    const float b0v = bsm[jc], b1v = bsm[jc + 1];
                    const float v00 = acc[mf][nf][0] + b0v, v01 = acc[mf][nf][1] + b1v;
                    const float v10 = acc[mf][nf][2] + b0v, v11 = acc[mf][nf][3] + b1v;
                    ss0 += v00 * v00 + v01 * v01;
                    ss1 += v10 * v10 + v11 * v11;
                    const int unit = jblk * 8 + wn * 4 + nf;
                    *(unsigned*)(KP + SWZB(r0,     unit) + tid4 * 4) = pkbf(v00, v01);
                    *(unsigned*)(KP + SWZB(r0 + 8, unit) + tid4 * 4) = pkbf(v10, v11);
                }
                ss0 += __shfl_xor_sync(0xffffffffu, ss0, 1);
                ss0 += __shfl_xor_sync(0xffffffffu, ss0, 2);
                ss1 += __shfl_xor_sync(0xffffffffu, ss1, 1);
                ss1 += __shfl_xor_sync(0xffffffffu, ss1, 2);
                if (tid4 == 0) {
                    atomicAdd(&rowss[r0], ss0);
                    atomicAdd(&rowss[r0 + 8], ss1);
                }
            }
            __syncthreads();
            if (jblk < 2)       { WP_ISSUE(jblk + 2, jblk & 1); cp_commit(); }
            else if (jblk == 2) { Q_ISSUE_HALF(0); cp_commit(); }
            else                { Q_ISSUE_HALF(1); cp_commit(); }
        }
    }
    cp_wait0();
    if (t < 128) rowss[t] = 1.0f / fmaxf(sqrtf(rowss[t]), 1e-12f);
    __syncthreads();

    // ---- Phase 2: logits[s][l] = (kp . q) * invnorm[s]; candidate collection ----
    const int wm = wid & 3, wn = wid >> 2;   // 4 s-groups x 2 l-groups(64)
    float acc[2][8][4];
#pragma unroll
    for (int mf = 0; mf < 2; ++mf)
#pragma unroll
        for (int nf = 0; nf < 8; ++nf)
#pragma unroll
            for (int c = 0; c < 4; ++c) acc[mf][nf][c] = 0.f;

#pragma unroll
    for (int kk = 0; kk < 16; ++kk) {
        unsigned a[2][4];
#pragma unroll
        for (int mf = 0; mf < 2; ++mf) {
            const int r0 = wm * 32 + mf * 16 + g;
            a[mf][0] = *(const unsigned*)(KP + SWZB(r0,     2 * kk)     + tid4 * 4);
            a[mf][1] = *(const unsigned*)(KP + SWZB(r0 + 8, 2 * kk)     + tid4 * 4);
            a[mf][2] = *(const unsigned*)(KP + SWZB(r0,     2 * kk + 1) + tid4 * 4);
            a[mf][3] = *(const unsigned*)(KP + SWZB(r0 + 8, 2 * kk + 1) + tid4 * 4);
        }
#pragma unroll
        for (int nf = 0; nf < 8; ++nf) {
            const int c = wn * 64 + nf * 8 + g;
            const unsigned b0 = *(const unsigned*)(WQ + SWZB(c, 2 * kk)     + tid4 * 4);
            const unsigned b1 = *(const unsigned*)(WQ + SWZB(c, 2 * kk + 1) + tid4 * 4);
            mma_bf16(acc[0][nf], a[0], b0, b1);
            mma_bf16(acc[1][nf], a[1], b0, b1);
        }
    }

    // scale by 1/norm
#pragma unroll
    for (int mf = 0; mf < 2; ++mf) {
        const int r0 = wm * 32 + mf * 16 + g;
        const float inv0 = rowss[r0], inv1 = rowss[r0 + 8];
#pragma unroll
        for (int nf = 0; nf < 8; ++nf) {
            acc[mf][nf][0] *= inv0; acc[mf][nf][1] *= inv0;
            acc[mf][nf][2] *= inv1; acc[mf][nf][3] *= inv1;
        }
    }

    // CTA-local per-l max
#pragma unroll
    for (int nf = 0; nf < 8; ++nf) {
        float m0 = fmaxf(fmaxf(acc[0][nf][0], acc[0][nf][2]),
                         fmaxf(acc[1][nf][0], acc[1][nf][2]));
        float m1 = fmaxf(fmaxf(acc[0][nf][1], acc[0][nf][3]),
                         fmaxf(acc[1][nf][1], acc[1][nf][3]));
#pragma unroll
        for (int off = 4; off < 32; off <<= 1) {
            m0 = fmaxf(m0, __shfl_xor_sync(0xffffffffu, m0, off));
            m1 = fmaxf(m1, __shfl_xor_sync(0xffffffffu, m1, off));
        }
        if (lane < 4) {
            const int lc = wn * 64 + nf * 8 + 2 * lane;
            atomicMax(&amax_s[lc],     fmap(m0));
            atomicMax(&amax_s[lc + 1], fmap(m1));
        }
    }
    __syncthreads();
    if (t < 128) {
        atomicMax(&g_amax[t * 8 + n], amax_s[t]);
        thr_s[t] = funmap(amax_s[t]) - MARGIN;
    }
    __syncthreads();

    // count survivors
    int cnt = 0;
#pragma unroll
    for (int mf = 0; mf < 2; ++mf)
#pragma unroll
        for (int nf = 0; nf < 8; ++nf)
#pragma unroll
            for (int c = 0; c < 4; ++c) {
                const int lc = wn * 64 + nf * 8 + 2 * tid4 + (c & 1);
                if (acc[mf][nf][c] >= thr_s[lc]) ++cnt;
            }
    int incl = cnt;
#pragma unroll
    for (int off = 1; off < 32; off <<= 1) {
        const int v = __shfl_up_sync(0xffffffffu, incl, off);
        if (lane >= off) incl += v;
    }
    if (lane == 31) wtot[wid] = (unsigned)incl;
    __syncthreads();
    if (t == 0) {
        unsigned tot = 0;
#pragma unroll
        for (int w = 0; w < 8; ++w) { woff[w] = tot; tot += wtot[w]; }
        base_s = atomicAdd(&g_npool, tot);
    }
    __syncthreads();
    unsigned p = base_s + woff[wid] + (unsigned)(incl - cnt);

#pragma unroll
    for (int mf = 0; mf < 2; ++mf)
#pragma unroll
        for (int nf = 0; nf < 8; ++nf)
#pragma unroll
            for (int c = 0; c < 4; ++c) {
                const int lc = wn * 64 + nf * 8 + 2 * tid4 + (c & 1);
                const float v = acc[mf][nf][c];
                if (v >= thr_s[lc]) {
                    const int sr = s0 + wm * 32 + mf * 16 + g + ((c >= 2) ? 8 : 0);
                    if (p < POOL_CAP)
                        g_pool[p] = make_uint2(((unsigned)sr << 10) |
                                               ((unsigned)lc << 3) | (unsigned)n,
                                               __float_as_uint(v));
                    ++p;
                }
            }
}

// ---------------- K4: filter pool against global approx max ----------------
__global__ __launch_bounds__(256) void filter_kernel()
{
    __shared__ float thr_s[LN_ROWS];
    const int t = threadIdx.x;
    for (int i = t; i < LN_ROWS; i += 256) thr_s[i] = funmap(g_amax[i]) - MARGIN;
    __syncthreads();
    const unsigned np = min(g_npool, (unsigned)POOL_CAP);
    for (unsigned idx = blockIdx.x * 256 + t; idx < np; idx += gridDim.x * 256) {
        const uint2 e = g_pool[idx];
        const unsigned l = (e.x >> 3) & 127u, n = e.x & 7u;
        if (__uint_as_float(e.y) >= thr_s[l * 8 + n]) {
            const unsigned pp = atomicAdd(&g_ncand, 1u);
            if (pp < CAND_CAP) g_cand[pp] = e.x;
        }
    }
}

// ---------------- K5: exact fp32 rescore of candidates ----------------
__global__ __launch_bounds__(256) void rescore_kernel(
    const float* __restrict__ mem, const float* __restrict__ pos,
    const float* __restrict__ Wp,  const float* __restrict__ bp)
{
    __shared__ float a_s[8][256];
    __shared__ float q_s[8][256];
    __shared__ unsigned cinfo[8];
    __shared__ float rss[8], rqd[8];
    __shared__ unsigned count_s;

    const int t = threadIdx.x, lane = t & 31, wid = t >> 5;
    if (t == 0) count_s = min(g_ncand, (unsigned)CAND_CAP);
    __syncthreads();
    const unsigned count = count_s;

    for (unsigned chunk = blockIdx.x; chunk * 8u < count; chunk += gridDim.x) {
        __syncthreads();
#pragma unroll
        for (int ci = 0; ci < 8; ++ci) {
            const unsigned c = chunk * 8u + ci;
            const unsigned packed = g_cand[(c < count) ? c : chunk * 8u];
            const unsigned s = packed >> 10, n = packed & 7u;
            a_s[ci][t] = mem[((size_t)s * 8 + n) * 256 + t]
                       + pos[((size_t)s * 8 + n) * 256 + t];
            const unsigned l = (packed >> 3) & 127u;
            q_s[ci][t] = g_qproj[((size_t)l * 8 + n) * 256 + t];
            if (t == ci) cinfo[ci] = packed;
        }
        __syncthreads();

        float acc[8];
#pragma unroll
        for (int ci = 0; ci < 8; ++ci) acc[ci] = bp[t];
        const float4* w4 = (const float4*)&Wp[(size_t)t * 256];
#pragma unroll 4
        for (int k4 = 0; k4 < 64; ++k4) {
            const float4 w = w4[k4];
#pragma unroll
            for (int ci = 0; ci < 8; ++ci) {
                const float4 a = *(const float4*)&a_s[ci][k4 * 4];
                acc[ci] += a.x * w.x + a.y * w.y + a.z * w.z + a.w * w.w;
            }
        }

        for (int ci = 0; ci < 8; ++ci) {
            const float kp = acc[ci];
            float ss = kp * kp;
            float qd = q_s[ci][t] * kp;
#pragma unroll
            for (int off = 16; off > 0; off >>= 1) {
                ss += __shfl_xor_sync(0xffffffffu, ss, off);
                qd += __shfl_xor_sync(0xffffffffu, qd, off);
            }
            __syncthreads();
            if (lane == 0) { rss[wid] = ss; rqd[wid] = qd; }
            __syncthreads();
            if (t == 0) {
                const unsigned c = chunk * 8u + ci;
                if (c < count) {
                    float S = 0.f, Q = 0.f;
#pragma unroll
                    for (int w = 0; w < 8; ++w) { S += rss[w]; Q += rqd[w]; }
                    const float logit = Q / fmaxf(sqrtf(S), 1e-12f);
                    const unsigned packed = cinfo[ci];
                    const unsigned s = packed >> 10, l = (packed >> 3) & 127u, nn = packed & 7u;
                    const unsigned long long key =
                        ((unsigned long long)fmap(logit) << 32) |
                        (unsigned long long)(0xFFFFFFFFu - s);
                    atomicMax(&g_argmax[l * 8 + nn], key);
                }
            }
        }
    }
}

// ---------------- K6: gather + lazy v_proj + Wo + residual + LayerNorm ----------------
__global__ __launch_bounds__(256) void finalize_kernel(
    const float* __restrict__ tgt,   const float* __restrict__ memory,
    const float* __restrict__ pos,
    const float* __restrict__ Wp,    const float* __restrict__ bp,
    const float* __restrict__ Wv,    const float* __restrict__ bv,
    const float* __restrict__ Wo,    const float* __restrict__ bo,
    const float* __restrict__ gamma, const float* __restrict__ beta,
    float* __restrict__ out)
{
    __shared__ float a[256];
    __shared__ float tmp[256];
    __shared__ float red[8];
    __shared__ int   s_sel;
    __shared__ float mu_s, var_s;

    const int t    = threadIdx.x;
    const int pair = blockIdx.x;           // = l*8 + n
    const int lane = t & 31, wid = t >> 5;

    if (t == 0) {
        const unsigned long long key = g_argmax[pair];
        s_sel = (int)(0xFFFFFFFFu - (unsigned)(key & 0xFFFFFFFFull));
    }
    __syncthreads();

    const int n    = pair & 7;
    const int rowk = s_sel * 8 + n;
    a[t] = memory[(size_t)rowk * 256 + t] + pos[(size_t)rowk * 256 + t];
    __syncthreads();

    float acc = bp[t];
    {
        const float4* w4 = (const float4*)&Wp[(size_t)t * 256];
#pragma unroll 8
        for (int k = 0; k < 64; ++k) {
            const float4 w = w4[k];
            acc += a[k * 4 + 0] * w.x + a[k * 4 + 1] * w.y
                 + a[k * 4 + 2] * w.z + a[k * 4 + 3] * w.w;
        }
    }
    tmp[t] = acc;
    __syncthreads();

    acc = bv[t];
    {
        const float4* w4 = (const float4*)&Wv[(size_t)t * 256];
#pragma unroll 8
        for (int k = 0; k < 64; ++k) {
            const float4 w = w4[k];
            acc += tmp[k * 4 + 0] * w.x + tmp[k * 4 + 1] * w.y
                 + tmp[k * 4 + 2] * w.z + tmp[k * 4 + 3] * w.w;
        }
    }
    a[t] = acc;
    __syncthreads();

    acc = bo[t];
    {
        const float4* w4 = (const float4*)&Wo[(size_t)t * 256];
#pragma unroll 8
        for (int k = 0; k < 64; ++k) {
            const float4 w = w4[k];
            acc += a[k * 4 + 0] * w.x + a[k * 4 + 1] * w.y
                 + a[k * 4 + 2] * w.z + a[k * 4 + 3] * w.w;
        }
    }
    const float x = tgt[(size_t)pair * 256 + t] + acc;

    float s = x;
#pragma unroll
    for (int off = 16; off > 0; off >>= 1) s += __shfl_xor_sync(0xffffffffu, s, off);
    if (lane == 0) red[wid] = s;
    __syncthreads();
    if (t == 0) {
        float tot = 0.f;
#pragma unroll
        for (int i = 0; i < 8; ++i) tot += red[i];
        mu_s = tot * (1.0f / 256.0f);
    }
    __syncthreads();
    const float mu = mu_s;
    const float d  = x - mu;
    float s2 = d * d;
#pragma unroll
    for (int off = 16; off > 0; off >>= 1) s2 += __shfl_xor_sync(0xffffffffu, s2, off);
    __syncthreads();
    if (lane == 0) red[wid] = s2;
    __syncthreads();
    if (t == 0) {
        float tot = 0.f;
#pragma unroll
        for (int i = 0; i < 8; ++i) tot += red[i];
        var_s = tot * (1.0f / 256.0f);
    }
    __syncthreads();

    const float rstd = rsqrtf(var_s + 1e-5f);
    out[(size_t)pair * 256 + t] = d * rstd * gamma[t] + beta[t];
}

// ---------------- launch ----------------
extern "C" void kernel_launch(void* const* d_in, const int* in_sizes, int n_in,
                              void* d_out, int out_size)
{
    const float* tgt       = (const float*)d_in[0];
    const float* memory    = (const float*)d_in[1];
    const float* pos       = (const float*)d_in[2];
    const float* query_pos = (const float*)d_in[3];
    const float* Wq        = (const float*)d_in[4];
    const float* bq        = (const float*)d_in[5];
    const float* Wp        = (const float*)d_in[6];
    const float* bp        = (const float*)d_in[7];
    const float* Wv        = (const float*)d_in[8];
    const float* bv        = (const float*)d_in[9];
    const float* Wo        = (const float*)d_in[10];
    const float* bo        = (const float*)d_in[11];
    const float* gamma     = (const float*)d_in[12];
    const float* beta      = (const float*)d_in[13];
    float* out             = (float*)d_out;

    static int smem_set = 0;
    if (!smem_set) {
        cudaFuncSetAttribute(fused_kernel,
                             cudaFuncAttributeMaxDynamicSharedMemorySize, FU_SMEM);
        smem_set = 1;
    }

    init_kernel<<<4, 256>>>();
    wpconv_kernel<<<256, 256>>>(Wp);
    qproj_kernel<<<LN_ROWS / 8, 256>>>(tgt, query_pos, Wq, bq);
    fused_kernel<<<dim3(S_P / 128, N_B), 256, FU_SMEM>>>(memory, pos, bp);
    filter_kernel<<<512, 256>>>();
    rescore_kernel<<<512, 256>>>(memory, pos, Wp, bp);
    finalize_kernel<<<LN_ROWS, 256>>>(tgt, memory, pos, Wp, bp, Wv, bv, Wo, bo,
                                      gamma, beta, out);
}

// round 9
// speedup vs baseline: 3.0383x; 1.7687x over previous
#include <cuda_runtime.h>
#include <cuda_bf16.h>
#include <cstdint>

// Problem constants
#define L_Q  128
#define N_B  8
#define S_P  16384
#define C_D  256
#define SN_ROWS (S_P * N_B)   // 131072
#define LN_ROWS (L_Q * N_B)   // 1024
#define MARGIN  0.30f
#define CAND_CAP (1u << 20)
#define POOL_CAP (1u << 22)

// ---------------- scratch ----------------
__device__ float          g_qproj[LN_ROWS * C_D];            // exact fp32 q_proj [l*8+n][c]
__device__ __nv_bfloat16  g_qb[LN_ROWS * C_D];               // bf16 q_proj [n][l][c]
__device__ __nv_bfloat16  g_wpb[C_D * C_D];                  // bf16 Wp
__device__ uint2          g_pool[POOL_CAP];                  // {packed, logit_bits}
__device__ unsigned       g_npool;
__device__ unsigned       g_amax[LN_ROWS];                   // mapped-float global approx max
__device__ unsigned       g_cand[CAND_CAP];                  // packed (s<<10)|(l<<3)|n
__device__ unsigned       g_ncand;
__device__ unsigned long long g_argmax[LN_ROWS];             // packed (mapped_exact<<32)|~s

// ---------------- helpers ----------------
static __device__ __forceinline__ unsigned fmap(float x) {
    unsigned m = __float_as_uint(x);
    return (m & 0x80000000u) ? ~m : (m | 0x80000000u);
}
static __device__ __forceinline__ float funmap(unsigned u) {
    return __uint_as_float((u & 0x80000000u) ? (u ^ 0x80000000u) : ~u);
}
static __device__ __forceinline__ void mma_bf16(float c[4], const unsigned a[4],
                                                unsigned b0, unsigned b1) {
    asm volatile("mma.sync.aligned.m16n8k16.row.col.f32.bf16.bf16.f32 "
                 "{%0,%1,%2,%3}, {%4,%5,%6,%7}, {%8,%9}, {%0,%1,%2,%3};"
                 : "+f"(c[0]), "+f"(c[1]), "+f"(c[2]), "+f"(c[3])
                 : "r"(a[0]), "r"(a[1]), "r"(a[2]), "r"(a[3]), "r"(b0), "r"(b1));
}
static __device__ __forceinline__ void cp16(void* smem_dst, const void* gsrc) {
    unsigned d = (unsigned)__cvta_generic_to_shared(smem_dst);
    asm volatile("cp.async.cg.shared.global [%0], [%1], 16;\n" :: "r"(d), "l"(gsrc));
}
static __device__ __forceinline__ void cp_commit() {
    asm volatile("cp.async.commit_group;\n" ::: "memory");
}
static __device__ __forceinline__ void cp_wait1() {
    asm volatile("cp.async.wait_group 1;\n" ::: "memory");
}
static __device__ __forceinline__ void cp_wait0() {
    asm volatile("cp.async.wait_group 0;\n" ::: "memory");
}
static __device__ __forceinline__ unsigned pkbf(float x, float y) {
    __nv_bfloat162 h = __floats2bfloat162_rn(x, y);
    return *(unsigned*)&h;
}

// Swizzled byte offset inside a [rows][256 bf16] tile: 32 16B-units per 512B row;
// XOR of low-3 unit bits with (row&7) => conflict-free 8-row fragment access.
#define SWZB(row, unit) (((row) << 9) + ((((unit) ^ ((row) & 7))) << 4))

// ---------------- K0: init ----------------
__global__ void init_kernel() {
    int i = blockIdx.x * blockDim.x + threadIdx.x;
    if (i < LN_ROWS) { g_amax[i] = 0u; g_argmax[i] = 0ull; }
    if (i == 0) { g_ncand = 0u; g_npool = 0u; }
}

// ---------------- K0b: Wp -> bf16 ----------------
__global__ void wpconv_kernel(const float* __restrict__ Wp) {
    int i = blockIdx.x * blockDim.x + threadIdx.x;   // 65536
    g_wpb[i] = __float2bfloat16(Wp[i]);
}

// ---------------- K1: exact fp32 q_proj (+ bf16 copy, [n][l][c]) ----------------
__global__ __launch_bounds__(256) void qproj_kernel(
    const float* __restrict__ tgt, const float* __restrict__ qpos,
    const float* __restrict__ Wq,  const float* __restrict__ bq)
{
    __shared__ float a_s[8][256];
    const int t  = threadIdx.x;
    const int r0 = blockIdx.x * 8;
#pragma unroll
    for (int r = 0; r < 8; ++r)
        a_s[r][t] = tgt[(size_t)(r0 + r) * 256 + t] + qpos[(size_t)(r0 + r) * 256 + t];
    __syncthreads();
    float acc[8];
#pragma unroll
    for (int r = 0; r < 8; ++r) acc[r] = bq[t];
    const float4* w4 = (const float4*)&Wq[(size_t)t * 256];
#pragma unroll 4
    for (int k4 = 0; k4 < 64; ++k4) {
        const float4 w = w4[k4];
#pragma unroll
        for (int r = 0; r < 8; ++r) {
            const float4 a = *(const float4*)&a_s[r][k4 * 4];
            acc[r] += a.x * w.x + a.y * w.y + a.z * w.z + a.w * w.w;
        }
    }
#pragma unroll
    for (int r = 0; r < 8; ++r) {
        const int row = r0 + r;            // = l*8 + n
        const int l = row >> 3, n = row & 7;
        g_qproj[(size_t)row * 256 + t] = acc[r];
        g_qb[((size_t)n * L_Q + l) * 256 + t] = __float2bfloat16(acc[r]);
    }
}

// ---------------- K2: FUSED k_proj + normalize + logits + candidates (512 thr) ----
// CTA = (128 s-rows, batch n). grid (128, 8), 16 warps.
//   AS [0,      65536): A = bf16(mem+pos), 128x256, swizzled
//   WQ [65536, 131072): phase1 = Wp col-block double buffer (2 x 32KB)
//                       phase2 = q tile 128x256 bf16, swizzled
//   KP [131072,196608): kp tile 128x256 bf16 (bias added, unnormalized), swizzled
#define FU_SMEM 196608
__global__ __launch_bounds__(512, 1) void fused_kernel(
    const float* __restrict__ mem, const float* __restrict__ pos,
    const float* __restrict__ bp)
{
    extern __shared__ char sm[];
    char* AS = sm;
    char* WQ = sm + 65536;
    char* KP = sm + 131072;
    __shared__ float    rowss[128];
    __shared__ float    bsm[256];
    __shared__ unsigned amax_s[128];
    __shared__ float    thr_s[128];
    __shared__ unsigned wtot[16], woff[16], base_s;

    const int t = threadIdx.x, lane = t & 31, wid = t >> 5;
    const int g = lane >> 2, tid4 = lane & 3;
    const int s0 = blockIdx.x * 128;
    const int n  = blockIdx.y;

    if (t < 128) { rowss[t] = 0.f; amax_s[t] = 0u; }
    if (t < 256) bsm[t] = bp[t];

#define WP_ISSUE(blk, buf)                                                        \
    {                                                                             \
        _Pragma("unroll")                                                         \
        for (int i = 0; i < 4; ++i) {                                             \
            const int id = t + i * 512, r = id >> 5, u = id & 31;                 \
            cp16(WQ + (buf) * 32768 + SWZB(r, u),                                 \
                 &g_wpb[((blk) * 64 + r) * 256 + u * 8]);                         \
        }                                                                         \
    }
#define Q_ISSUE_HALF(h)                                                           \
    {                                                                             \
        _Pragma("unroll")                                                         \
        for (int i = 0; i < 4; ++i) {                                             \
            const int id = t + i * 512, rq = (h) * 64 + (id >> 5), u = id & 31;   \
            cp16(WQ + SWZB(rq, u), &g_qb[((size_t)n * L_Q + rq) * 256 + u * 8]);  \
        }                                                                         \
    }

    WP_ISSUE(0, 0); cp_commit();

    // ---- A staging: bf16(mem+pos), swizzled ----
#pragma unroll
    for (int i = 0; i < 8; ++i) {
        const int id = t + i * 512, r = id >> 5, u = id & 31;
        const size_t base = ((size_t)(s0 + r) * 8 + n) * 256 + u * 8;
        const float4 m0 = *(const float4*)&mem[base];
        const float4 m1 = *(const float4*)&mem[base + 4];
        const float4 p0 = *(const float4*)&pos[base];
        const float4 p1 = *(const float4*)&pos[base + 4];
        uint4 v;
        v.x = pkbf(m0.x + p0.x, m0.y + p0.y);
        v.y = pkbf(m0.z + p0.z, m0.w + p0.w);
        v.z = pkbf(m1.x + p1.x, m1.y + p1.y);
        v.w = pkbf(m1.z + p1.z, m1.w + p1.w);
        *(uint4*)(AS + SWZB(r, u)) = v;
    }
    WP_ISSUE(1, 1); cp_commit();

    // ---- Phase 1: kp = A @ Wp^T (+bias), 4 col-blocks of 64 ----
    {
        const int wm = wid & 3, wn = wid >> 2;   // 4 s-groups(32) x 4 j-groups(16)
        for (int jblk = 0; jblk < 4; ++jblk) {
            cp_wait1();
            __syncthreads();
            const char* WB = WQ + (jblk & 1) * 32768;
            float acc[2][2][4];
#pragma unroll
            for (int mf = 0; mf < 2; ++mf)
#pragma unroll
                for (int nf = 0; nf < 2; ++nf)
#pragma unroll
                    for (int c = 0; c < 4; ++c) acc[mf][nf][c] = 0.f;
#pragma unroll
            for (int kk = 0; kk < 16; ++kk) {
                unsigned a[2][4];
#pragma unroll
                for (int mf = 0; mf < 2; ++mf) {
                    const int r0 = wm * 32 + mf * 16 + g;
                    a[mf][0] = *(const unsigned*)(AS + SWZB(r0,     2 * kk)     + tid4 * 4);
                    a[mf][1] = *(const unsigned*)(AS + SWZB(r0 + 8, 2 * kk)     + tid4 * 4);
                    a[mf][2] = *(const unsigned*)(AS + SWZB(r0,     2 * kk + 1) + tid4 * 4);
                    a[mf][3] = *(const unsigned*)(AS + SWZB(r0 + 8, 2 * kk + 1) + tid4 * 4);
                }
#pragma unroll
                for (int nf = 0; nf < 2; ++nf) {
                    const int c = wn * 16 + nf * 8 + g;
                    const unsigned b0 = *(const unsigned*)(WB + SWZB(c, 2 * kk)     + tid4 * 4);
                    const unsigned b1 = *(const unsigned*)(WB + SWZB(c, 2 * kk + 1) + tid4 * 4);
                    mma_bf16(acc[0][nf], a[0], b0, b1);
                    mma_bf16(acc[1][nf], a[1], b0, b1);
                }
            }
            // epilogue: +bias, sum-sq, store bf16 kp tile
#pragma unroll
            for (int mf = 0; mf < 2; ++mf) {
                const int r0 = wm * 32 + mf * 16 + g;
                float ss0 = 0.f, ss1 = 0.f;
#pragma unroll
                for (int nf = 0; nf < 2; ++nf) {
                    const int jc = jblk * 64 + wn * 16 + nf * 8 + 2 * tid4;
                    const float b0v = bsm[jc], b1v = bsm[jc + 1];
                    const float v00 = acc[mf][nf][0] + b0v, v01 = acc[mf][nf][1] + b1v;
                    const float v10 = acc[mf][nf][2] + b0v, v11 = acc[mf][nf][3] + b1v;
                    ss0 += v00 * v00 + v01 * v01;
                    ss1 += v10 * v10 + v11 * v11;
                    const int unit = jblk * 8 + wn * 2 + nf;
                    *(unsigned*)(KP + SWZB(r0,     unit) + tid4 * 4) = pkbf(v00, v01);
                    *(unsigned*)(KP + SWZB(r0 + 8, unit) + tid4 * 4) = pkbf(v10, v11);
                }
                ss0 += __shfl_xor_sync(0xffffffffu, ss0, 1);
                ss0 += __shfl_xor_sync(0xffffffffu, ss0, 2);
                ss1 += __shfl_xor_sync(0xffffffffu, ss1, 1);
                ss1 += __shfl_xor_sync(0xffffffffu, ss1, 2);
                if (tid4 == 0) {
                    atomicAdd(&rowss[r0], ss0);
                    atomicAdd(&rowss[r0 + 8], ss1);
                }
            }
            __syncthreads();
            if (jblk < 2)       { WP_ISSUE(jblk + 2, jblk & 1); cp_commit(); }
            else if (jblk == 2) { Q_ISSUE_HALF(0); cp_commit(); }
            else                { Q_ISSUE_HALF(1); cp_commit(); }
        }
    }
    cp_wait0();
    if (t < 128) rowss[t] = 1.0f / fmaxf(sqrtf(rowss[t]), 1e-12f);
    __syncthreads();

    // ---- Phase 2: logits[s][l] = (kp . q) * invnorm[s]; candidate collection ----
    const int wm = wid & 3, wn = wid >> 2;   // 4 s-groups(32) x 4 l-groups(32)
    float acc[2][4][4];
#pragma unroll
    for (int mf = 0; mf < 2; ++mf)
#pragma unroll
        for (int nf = 0; nf < 4; ++nf)
#pragma unroll
            for (int c = 0; c < 4; ++c) acc[mf][nf][c] = 0.f;

#pragma unroll
    for (int kk = 0; kk < 16; ++kk) {
        unsigned a[2][4];
#pragma unroll
        for (int mf = 0; mf < 2; ++mf) {
            const int r0 = wm * 32 + mf * 16 + g;
            a[mf][0] = *(const unsigned*)(KP + SWZB(r0,     2 * kk)     + tid4 * 4);
            a[mf][1] = *(const unsigned*)(KP + SWZB(r0 + 8, 2 * kk)     + tid4 * 4);
            a[mf][2] = *(const unsigned*)(KP + SWZB(r0,     2 * kk + 1) + tid4 * 4);
            a[mf][3] = *(const unsigned*)(KP + SWZB(r0 + 8, 2 * kk + 1) + tid4 * 4);
        }
#pragma unroll
        for (int nf = 0; nf < 4; ++nf) {
            const int c = wn * 32 + nf * 8 + g;
            const unsigned b0 = *(const unsigned*)(WQ + SWZB(c, 2 * kk)     + tid4 * 4);
            const unsigned b1 = *(const unsigned*)(WQ + SWZB(c, 2 * kk + 1) + tid4 * 4);
            mma_bf16(acc[0][nf], a[0], b0, b1);
            mma_bf16(acc[1][nf], a[1], b0, b1);
        }
    }

    // scale by 1/norm
#pragma unroll
    for (int mf = 0; mf < 2; ++mf) {
        const int r0 = wm * 32 + mf * 16 + g;
        const float inv0 = rowss[r0], inv1 = rowss[r0 + 8];
#pragma unroll
        for (int nf = 0; nf < 4; ++nf) {
            acc[mf][nf][0] *= inv0; acc[mf][nf][1] *= inv0;
            acc[mf][nf][2] *= inv1; acc[mf][nf][3] *= inv1;
        }
    }

    // CTA-local per-l max
#pragma unroll
    for (int nf = 0; nf < 4; ++nf) {
        float m0 = fmaxf(fmaxf(acc[0][nf][0], acc[0][nf][2]),
                         fmaxf(acc[1][nf][0], acc[1][nf][2]));
        float m1 = fmaxf(fmaxf(acc[0][nf][1], acc[0][nf][3]),
                         fmaxf(acc[1][nf][1], acc[1][nf][3]));
#pragma unroll
        for (int off = 4; off < 32; off <<= 1) {
            m0 = fmaxf(m0, __shfl_xor_sync(0xffffffffu, m0, off));
            m1 = fmaxf(m1, __shfl_xor_sync(0xffffffffu, m1, off));
        }
        if (lane < 4) {
            const int lc = wn * 32 + nf * 8 + 2 * lane;
            atomicMax(&amax_s[lc],     fmap(m0));
            atomicMax(&amax_s[lc + 1], fmap(m1));
        }
    }
    __syncthreads();
    if (t < 128) {
        atomicMax(&g_amax[t * 8 + n], amax_s[t]);
        thr_s[t] = funmap(amax_s[t]) - MARGIN;
    }
    __syncthreads();

    // count survivors
    int cnt = 0;
#pragma unroll
    for (int mf = 0; mf < 2; ++mf)
#pragma unroll
        for (int nf = 0; nf < 4; ++nf)
#pragma unroll
            for (int c = 0; c < 4; ++c) {
                const int lc = wn * 32 + nf * 8 + 2 * tid4 + (c & 1);
                if (acc[mf][nf][c] >= thr_s[lc]) ++cnt;
            }
    int incl = cnt;
#pragma unroll
    for (int off = 1; off < 32; off <<= 1) {
        const int v = __shfl_up_sync(0xffffffffu, incl, off);
        if (lane >= off) incl += v;
    }
    if (lane == 31) wtot[wid] = (unsigned)incl;
    __syncthreads();
    if (t == 0) {
        unsigned tot = 0;
#pragma unroll
        for (int w = 0; w < 16; ++w) { woff[w] = tot; tot += wtot[w]; }
        base_s = atomicAdd(&g_npool, tot);
    }
    __syncthreads();
    unsigned p = base_s + woff[wid] + (unsigned)(incl - cnt);

#pragma unroll
    for (int mf = 0; mf < 2; ++mf)
#pragma unroll
        for (int nf = 0; nf < 4; ++nf)
#pragma unroll
            for (int c = 0; c < 4; ++c) {
                const int lc = wn * 32 + nf * 8 + 2 * tid4 + (c & 1);
                const float v = acc[mf][nf][c];
                if (v >= thr_s[lc]) {
                    const int sr = s0 + wm * 32 + mf * 16 + g + ((c >= 2) ? 8 : 0);
                    if (p < POOL_CAP)
                        g_pool[p] = make_uint2(((unsigned)sr << 10) |
                                               ((unsigned)lc << 3) | (unsigned)n,
                                               __float_as_uint(v));
                    ++p;
                }
            }
}

// ---------------- K4: filter pool against global approx max ----------------
__global__ __launch_bounds__(256) void filter_kernel()
{
    __shared__ float thr_s[LN_ROWS];
    const int t = threadIdx.x;
    for (int i = t; i < LN_ROWS; i += 256) thr_s[i] = funmap(g_amax[i]) - MARGIN;
    __syncthreads();
    const unsigned np = min(g_npool, (unsigned)POOL_CAP);
    for (unsigned idx = blockIdx.x * 256 + t; idx < np; idx += gridDim.x * 256) {
        const uint2 e = g_pool[idx];
        const unsigned l = (e.x >> 3) & 127u, n = e.x & 7u;
        if (__uint_as_float(e.y) >= thr_s[l * 8 + n]) {
            const unsigned pp = atomicAdd(&g_ncand, 1u);
            if (pp < CAND_CAP) g_cand[pp] = e.x;
        }
    }
}

// ---------------- K5: exact fp32 rescore, batched 32 candidates/CTA ----------------
// smem: A [32][256] f32 (32KB) | WT [32][257] f32 k-major (32.9KB) | KPS [32][257] (32.9KB)
#define RS_SMEM (32768 + 32896 + 32896)
__global__ __launch_bounds__(256, 1) void rescore_kernel(
    const float* __restrict__ mem, const float* __restrict__ pos,
    const float* __restrict__ Wp,  const float* __restrict__ bp)
{
    extern __shared__ char rsm[];
    float* A   = (float*)rsm;                    // [32][256]
    float* WT  = (float*)(rsm + 32768);          // [kk][o], stride 257
    float* KPS = (float*)(rsm + 65664);          // [ci][t], stride 257
    __shared__ unsigned meta[32];
    __shared__ unsigned count_s;

    const int t = threadIdx.x, lane = t & 31, wid = t >> 5;
    if (t == 0) count_s = min(g_ncand, (unsigned)CAND_CAP);
    __syncthreads();
    const unsigned count = count_s;
    const unsigned nchunks = (count + 31u) >> 5;

    for (unsigned chunk = blockIdx.x; chunk < nchunks; chunk += gridDim.x) {
        __syncthreads();
        if (t < 32)
            meta[t] = (chunk * 32u + t < count) ? g_cand[chunk * 32u + t] : 0xFFFFFFFFu;
        __syncthreads();

        // stage A rows (coalesced per row)
#pragma unroll 4
        for (int ci = 0; ci < 32; ++ci) {
            const unsigned pk = meta[ci];
            if (pk != 0xFFFFFFFFu) {
                const size_t rowk = ((size_t)(pk >> 10) * 8 + (pk & 7u)) * 256;
                A[ci * 256 + t] = mem[rowk + t] + pos[rowk + t];
            }
        }

        float acc[32];
        const float bias = bp[t];
#pragma unroll
        for (int ci = 0; ci < 32; ++ci) acc[ci] = bias;

        for (int kt = 0; kt < 8; ++kt) {
            __syncthreads();
            // stage WT[k][o] (coalesced global read, padded smem write)
#pragma unroll
            for (int i = 0; i < 8; ++i) {
                const int id = t + i * 256, o = id >> 3, k4 = id & 7;
                const float4 w = *(const float4*)&Wp[(size_t)o * 256 + kt * 32 + k4 * 4];
                WT[(k4 * 4 + 0) * 257 + o] = w.x;
                WT[(k4 * 4 + 1) * 257 + o] = w.y;
                WT[(k4 * 4 + 2) * 257 + o] = w.z;
                WT[(k4 * 4 + 3) * 257 + o] = w.w;
            }
            __syncthreads();
            float wt[32];
#pragma unroll
            for (int kk = 0; kk < 32; ++kk) wt[kk] = WT[kk * 257 + t];
#pragma unroll 4
            for (int ci = 0; ci < 32; ++ci) {
                const float4* a4 = (const float4*)&A[ci * 256 + kt * 32];
#pragma unroll
                for (int q = 0; q < 8; ++q) {
                    const float4 av = a4[q];
                    acc[ci] += av.x * wt[q * 4 + 0] + av.y * wt[q * 4 + 1]
                             + av.z * wt[q * 4 + 2] + av.w * wt[q * 4 + 3];
                }
            }
        }
        __syncthreads();
#pragma unroll
        for (int ci = 0; ci < 32; ++ci) KPS[ci * 257 + t] = acc[ci];
        __syncthreads();

        // per-warp reduction: warp handles 4 candidates
#pragma unroll
        for (int cc = 0; cc < 4; ++cc) {
            const int ci = wid * 4 + cc;
            const unsigned pk = meta[ci];
            if (pk == 0xFFFFFFFFu) continue;
            const unsigned s = pk >> 10, l = (pk >> 3) & 127u, n = pk & 7u;
            const float* qrow = &g_qproj[((size_t)l * 8 + n) * 256];
            float ss = 0.f, qd = 0.f;
#pragma unroll
            for (int j = 0; j < 8; ++j) {
                const float kv = KPS[ci * 257 + lane + 32 * j];
                ss += kv * kv;
                qd += qrow[lane + 32 * j] * kv;
            }
#pragma unroll
            for (int off = 16; off > 0; off >>= 1) {
                ss += __shfl_xor_sync(0xffffffffu, ss, off);
                qd += __shfl_xor_sync(0xffffffffu, qd, off);
            }
            if (lane == 0) {
                const float logit = qd / fmaxf(sqrtf(ss), 1e-12f);
                const unsigned long long key =
                    ((unsigned long long)fmap(logit) << 32) |
                    (unsigned long long)(0xFFFFFFFFu - s);
                atomicMax(&g_argmax[l * 8 + n], key);
            }
        }
    }
}

// ---------------- K6: batched finalize — 64 CTAs x 16 rows ----------------
// Every thread computes output channel t for ALL 16 rows (acc[16]).
// smem: BUF0 [16][256] f32 | BUF1 [16][256] f32 | WT [32][257] f32
#define FIN_SMEM (16384 + 16384 + 32896)
__global__ __launch_bounds__(256, 1) void finalize_kernel(
    const float* __restrict__ tgt,   const float* __restrict__ memory,
    const float* __restrict__ pos,
    const float* __restrict__ Wp,    const float* __restrict__ bp,
    const float* __restrict__ Wv,    const float* __restrict__ bv,
    const float* __restrict__ Wo,    const float* __restrict__ bo,
    const float* __restrict__ gamma, const float* __restrict__ beta,
    float* __restrict__ out)
{
    extern __shared__ char fsm[];
    float* BUF0 = (float*)fsm;                    // [16][256]
    float* BUF1 = (float*)(fsm + 16384);          // [16][256]
    float* WT   = (float*)(fsm + 32768);          // [32][257]
    __shared__ int sel_s[16];

    const int t = threadIdx.x, lane = t & 31, wid = t >> 5;
    const int base = blockIdx.x * 16;

    if (t < 16) {
        const unsigned long long key = g_argmax[base + t];
        sel_s[t] = (int)(0xFFFFFFFFu - (unsigned)(key & 0xFFFFFFFFull));
    }
    __syncthreads();

    // gather selected rows: BUF0[r][t] = (memory+pos)[sel_s[r]*8 + n][t]
#pragma unroll
    for (int r = 0; r < 16; ++r) {
        const size_t rowk = ((size_t)sel_s[r] * 8 + ((base + r) & 7)) * 256;
        BUF0[r * 256 + t] = memory[rowk + t] + pos[rowk + t];
    }

    const float* Ws[3] = {Wp, Wv, Wo};
    const float* bs[3] = {bp, bv, bo};
#pragma unroll
    for (int layer = 0; layer < 3; ++layer) {
        const float* W   = Ws[layer];
        float* INB  = (layer & 1) ? BUF1 : BUF0;
        float* OUTB = (layer & 1) ? BUF0 : BUF1;
        float acc[16];
#pragma unroll
        for (int r = 0; r < 16; ++r) acc[r] = 0.f;

        for (int kt = 0; kt < 8; ++kt) {
            __syncthreads();
            // stage WT[k][o] for this k-tile (coalesced global read)
#pragma unroll
            for (int i = 0; i < 8; ++i) {
                const int id = t + i * 256, o = id >> 3, k4 = id & 7;
                const float4 w = *(const float4*)&W[(size_t)o * 256 + kt * 32 + k4 * 4];
                WT[(k4 * 4 + 0) * 257 + o] = w.x;
                WT[(k4 * 4 + 1) * 257 + o] = w.y;
                WT[(k4 * 4 + 2) * 257 + o] = w.z;
                WT[(k4 * 4 + 3) * 257 + o] = w.w;
            }
            __syncthreads();
            float wt[32];
#pragma unroll
            for (int kk = 0; kk < 32; ++kk) wt[kk] = WT[kk * 257 + t];
#pragma unroll
            for (int r = 0; r < 16; ++r) {
                const float4* a4 = (const float4*)&INB[r * 256 + kt * 32];
#pragma unroll
                for (int q = 0; q < 8; ++q) {
                    const float4 av = a4[q];
                    acc[r] += av.x * wt[q * 4 + 0] + av.y * wt[q * 4 + 1]
                            + av.z * wt[q * 4 + 2] + av.w * wt[q * 4 + 3];
                }
            }
        }
        __syncthreads();
        const float bias = bs[layer][t];
#pragma unroll
        for (int r = 0; r < 16; ++r)
            OUTB[r * 256 + t] = acc[r] + bias;
    }
    __syncthreads();

    // x = tgt + upd (upd in BUF1 after 3 layers); LayerNorm per row.
    // 8 warps x 2 rows each.
#pragma unroll
    for (int rr = 0; rr < 2; ++rr) {
        const int r = wid * 2 + rr;
        const int pair = base + r;
        float xv[8];
        float s = 0.f, s2 = 0.f;
#pragma unroll
        for (int j = 0; j < 8; ++j) {
            const int c = lane + 32 * j;
            xv[j] = tgt[(size_t)pair * 256 + c] + BUF1[r * 256 + c];
            s  += xv[j];
            s2 += xv[j] * xv[j];
        }
#pragma unroll
        for (int off = 16; off > 0; off >>= 1) {
            s  += __shfl_xor_sync(0xffffffffu, s,  off);
            s2 += __shfl_xor_sync(0xffffffffu, s2, off);
        }
        const float mu   = s * (1.0f / 256.0f);
        const float var  = s2 * (1.0f / 256.0f) - mu * mu;
        const float rstd = rsqrtf(var + 1e-5f);
#pragma unroll
        for (int j = 0; j < 8; ++j) {
            const int c = lane + 32 * j;
            out[(size_t)pair * 256 + c] = (xv[j] - mu) * rstd * gamma[c] + beta[c];
        }
    }
}

// ---------------- launch ----------------
extern "C" void kernel_launch(void* const* d_in, const int* in_sizes, int n_in,
                              void* d_out, int out_size)
{
    const float* tgt       = (const float*)d_in[0];
    const float* memory    = (const float*)d_in[1];
    const float* pos       = (const float*)d_in[2];
    const float* query_pos = (const float*)d_in[3];
    const float* Wq        = (const float*)d_in[4];
    const float* bq        = (const float*)d_in[5];
    const float* Wp        = (const float*)d_in[6];
    const float* bp        = (const float*)d_in[7];
    const float* Wv        = (const float*)d_in[8];
    const float* bv        = (const float*)d_in[9];
    const float* Wo        = (const float*)d_in[10];
    const float* bo        = (const float*)d_in[11];
    const float* gamma     = (const float*)d_in[12];
    const float* beta      = (const float*)d_in[13];
    float* out             = (float*)d_out;

    cudaFuncSetAttribute(fused_kernel,
                         cudaFuncAttributeMaxDynamicSharedMemorySize, FU_SMEM);
    cudaFuncSetAttribute(rescore_kernel,
                         cudaFuncAttributeMaxDynamicSharedMemorySize, RS_SMEM);
    cudaFuncSetAttribute(finalize_kernel,
                         cudaFuncAttributeMaxDynamicSharedMemorySize, FIN_SMEM);

    init_kernel<<<4, 256>>>();
    wpconv_kernel<<<256, 256>>>(Wp);
    qproj_kernel<<<LN_ROWS / 8, 256>>>(tgt, query_pos, Wq, bq);
    fused_kernel<<<dim3(S_P / 128, N_B), 512, FU_SMEM>>>(memory, pos, bp);
    filter_kernel<<<512, 256>>>();
    rescore_kernel<<<148, 256, RS_SMEM>>>(memory, pos, Wp, bp);
    finalize_kernel<<<LN_ROWS / 16, 256, FIN_SMEM>>>(tgt, memory, pos, Wp, bp,
                                                     Wv, bv, Wo, bo,
                                                     gamma, beta, out);
}

// round 13
// speedup vs baseline: 3.2096x; 1.0564x over previous
#include <cuda_runtime.h>
#include <cuda_bf16.h>
#include <cstdint>

// Problem constants
#define L_Q  128
#define N_B  8
#define S_P  16384
#define C_D  256
#define SN_ROWS (S_P * N_B)   // 131072
#define LN_ROWS (L_Q * N_B)   // 1024
#define MARGIN  0.30f
#define CAND_CAP (1u << 20)
#define POOL_CAP (1u << 22)

// ---------------- scratch ----------------
__device__ float          g_qproj[LN_ROWS * C_D];            // exact fp32 q_proj [l*8+n][c]
__device__ __nv_bfloat16  g_qb[LN_ROWS * C_D];               // bf16 q_proj [n][l][c]
__device__ __nv_bfloat16  g_wpb[C_D * C_D];                  // bf16 Wp
__device__ uint2          g_pool[POOL_CAP];                  // {packed, logit_bits}
__device__ unsigned       g_npool;
__device__ unsigned       g_amax[LN_ROWS];                   // mapped-float global approx max
__device__ unsigned       g_cand[CAND_CAP];                  // packed (s<<10)|(l<<3)|n
__device__ unsigned       g_ncand;
__device__ unsigned long long g_argmax[LN_ROWS];             // packed (mapped_exact<<32)|~s

// ---------------- helpers ----------------
static __device__ __forceinline__ unsigned fmap(float x) {
    unsigned m = __float_as_uint(x);
    return (m & 0x80000000u) ? ~m : (m | 0x80000000u);
}
static __device__ __forceinline__ float funmap(unsigned u) {
    return __uint_as_float((u & 0x80000000u) ? (u ^ 0x80000000u) : ~u);
}
static __device__ __forceinline__ void mma_bf16(float c[4], const unsigned a[4],
                                                unsigned b0, unsigned b1) {
    asm volatile("mma.sync.aligned.m16n8k16.row.col.f32.bf16.bf16.f32 "
                 "{%0,%1,%2,%3}, {%4,%5,%6,%7}, {%8,%9}, {%0,%1,%2,%3};"
                 : "+f"(c[0]), "+f"(c[1]), "+f"(c[2]), "+f"(c[3])
                 : "r"(a[0]), "r"(a[1]), "r"(a[2]), "r"(a[3]), "r"(b0), "r"(b1));
}
static __device__ __forceinline__ void ldsm4(unsigned* r, uint32_t addr) {
    asm volatile("ldmatrix.sync.aligned.m8n8.x4.shared.b16 {%0,%1,%2,%3}, [%4];"
                 : "=r"(r[0]), "=r"(r[1]), "=r"(r[2]), "=r"(r[3]) : "r"(addr));
}
static __device__ __forceinline__ void cp16(void* smem_dst, const void* gsrc) {
    unsigned d = (unsigned)__cvta_generic_to_shared(smem_dst);
    asm volatile("cp.async.cg.shared.global [%0], [%1], 16;\n" :: "r"(d), "l"(gsrc));
}
static __device__ __forceinline__ void cp_commit() {
    asm volatile("cp.async.commit_group;\n" ::: "memory");
}
static __device__ __forceinline__ void cp_wait0() {
    asm volatile("cp.async.wait_group 0;\n" ::: "memory");
}
static __device__ __forceinline__ unsigned pkbf(float x, float y) {
    __nv_bfloat162 h = __floats2bfloat162_rn(x, y);
    return *(unsigned*)&h;
}

// Swizzled byte offset inside a [rows][256 bf16] tile: 32 16B-units per 512B row;
// XOR of low-3 unit bits with (row&7) => conflict-free 8-row fragment access.
#define SWZB(row, unit) (((row) << 9) + ((((unit) ^ ((row) & 7))) << 4))
// 4B-pair store offset for (row m, even col jc):
#define KPB(m, jc) (((m) << 9) + (((((jc) >> 3) ^ ((m) & 7))) << 4) + (((jc) & 7) << 1))

// ---------------- K0: init + Wp->bf16 ----------------
__global__ void init_kernel(const float* __restrict__ Wp) {
    int i = blockIdx.x * blockDim.x + threadIdx.x;   // 65536
    g_wpb[i] = __float2bfloat16(Wp[i]);
    if (i < LN_ROWS) { g_amax[i] = 0u; g_argmax[i] = 0ull; }
    if (i == 0) { g_ncand = 0u; g_npool = 0u; }
}

// ---------------- K1: exact fp32 q_proj (+ bf16 copy, [n][l][c]) ----------------
__global__ __launch_bounds__(256) void qproj_kernel(
    const float* __restrict__ tgt, const float* __restrict__ qpos,
    const float* __restrict__ Wq,  const float* __restrict__ bq)
{
    __shared__ float a_s[8][256];
    const int t  = threadIdx.x;
    const int r0 = blockIdx.x * 8;
#pragma unroll
    for (int r = 0; r < 8; ++r)
        a_s[r][t] = tgt[(size_t)(r0 + r) * 256 + t] + qpos[(size_t)(r0 + r) * 256 + t];
    __syncthreads();
    float acc[8];
#pragma unroll
    for (int r = 0; r < 8; ++r) acc[r] = bq[t];
    const float4* w4 = (const float4*)&Wq[(size_t)t * 256];
#pragma unroll 4
    for (int k4 = 0; k4 < 64; ++k4) {
        const float4 w = w4[k4];
#pragma unroll
        for (int r = 0; r < 8; ++r) {
            const float4 a = *(const float4*)&a_s[r][k4 * 4];
            acc[r] += a.x * w.x + a.y * w.y + a.z * w.z + a.w * w.w;
        }
    }
#pragma unroll
    for (int r = 0; r < 8; ++r) {
        const int row = r0 + r;            // = l*8 + n
        const int l = row >> 3, n = row & 7;
        g_qproj[(size_t)row * 256 + t] = acc[r];
        g_qb[((size_t)n * L_Q + l) * 256 + t] = __float2bfloat16(acc[r]);
    }
}

// ---------------- K2: FUSED k_proj + normalize + logits + candidates ----------
// HMMA + ldmatrix version, 512 threads, warp grid 2(m) x 8(n), warp tile m64 x n16.
//   AS [0,      65536): A = bf16(mem+pos) 128x256, SWZB layout
//   WQ [65536, 131072): Wp half (128x256) / later q tile (128x256), SWZB
//   KP [131072,196608): kp tile 128x256 bf16 (bias added, unnormalized), SWZB
#define OF_ROW  196608
#define OF_BSM  197120
#define OF_AMX  198144
#define OF_THR  198656
#define OF_WT   199168
#define OF_WO   199232
#define OF_BASE 199296
#define FU_SMEM 199424
__global__ __launch_bounds__(512, 1) void fused_kernel(
    const float* __restrict__ mem, const float* __restrict__ pos,
    const float* __restrict__ bp)
{
    extern __shared__ char sm[];
    const uint32_t smu = (uint32_t)__cvta_generic_to_shared(sm);
    char* AS = sm;
    char* WQ = sm + 65536;
    char* KP = sm + 131072;
    float*    rowss  = (float*)(sm + OF_ROW);      // [128] sumsq -> invnorm
    float*    bsm    = (float*)(sm + OF_BSM);      // [256]
    unsigned* amax_s = (unsigned*)(sm + OF_AMX);   // [128]
    float*    thr_s  = (float*)(sm + OF_THR);      // [128]
    unsigned* wtot   = (unsigned*)(sm + OF_WT);    // [16]
    unsigned* woff   = (unsigned*)(sm + OF_WO);    // [16]
    unsigned* base_s = (unsigned*)(sm + OF_BASE);

    const uint32_t AS_u = smu, WQ_u = smu + 65536, KP_u = smu + 131072;
    const int t = threadIdx.x, lane = t & 31, wid = t >> 5;
    const int g = lane >> 2, tid4 = lane & 3;
    const int wm = wid >> 3;          // 0..1  (m rows, 64 each)
    const int wn = wid & 7;           // 0..7  (n cols, 16 each)
    const int s0 = blockIdx.x * 128;
    const int n  = blockIdx.y;

    // ldmatrix per-lane address constants
    const int xL    = lane & 7;
    const int aLrow = (lane & 7) + ((lane >> 3) & 1) * 8;  // A: mat&1 -> row half
    const int aDu   = lane >> 4;                            // A: mat>>1 -> unit inc
    const int bLrow = (lane & 7) + (lane >> 4) * 8;         // B: mat>>1 -> row half
    const int bDu   = (lane >> 3) & 1;                      // B: mat&1 -> unit inc

    if (t < 128) { rowss[t] = 0.f; amax_s[t] = 0u; }
    if (t < 256) bsm[t] = bp[t];

    // ---- stage Wp half 0 (async) ----
#pragma unroll
    for (int i = 0; i < 8; ++i) {
        const int id = t + i * 512, r = id >> 5, u = id & 31;
        cp16(WQ + SWZB(r, u), &g_wpb[(size_t)r * 256 + u * 8]);
    }
    cp_commit();

    // ---- stage A = bf16(mem+pos), SWZB (overlaps cp.async) ----
#pragma unroll
    for (int i = 0; i < 8; ++i) {
        const int id = t + i * 512, r = id >> 5, u = id & 31;
        const size_t base = ((size_t)(s0 + r) * 8 + n) * 256 + u * 8;
        const float4 m0 = *(const float4*)&mem[base];
        const float4 m1 = *(const float4*)&mem[base + 4];
        const float4 p0 = *(const float4*)&pos[base];
        const float4 p1 = *(const float4*)&pos[base + 4];
        uint4 v;
        v.x = pkbf(m0.x + p0.x, m0.y + p0.y);
        v.y = pkbf(m0.z + p0.z, m0.w + p0.w);
        v.z = pkbf(m1.x + p1.x, m1.y + p1.y);
        v.w = pkbf(m1.z + p1.z, m1.w + p1.w);
        *(uint4*)(AS + SWZB(r, u)) = v;
    }

    // A-fragment smem base addresses (per mf)
    uint32_t aBase[4], kpBase[4];
#pragma unroll
    for (int mf = 0; mf < 4; ++mf) {
        const int row = wm * 64 + mf * 16 + aLrow;
        aBase[mf]  = AS_u + (row << 9);
        kpBase[mf] = KP_u + (row << 9);
    }
    const uint32_t bBase = WQ_u + ((wn * 16 + bLrow) << 9);

    // ================= Phase 1: kp = A @ Wp^T (+bias), two 128-col halves ========
#pragma unroll 1
    for (int h = 0; h < 2; ++h) {
        cp_wait0();
        __syncthreads();
        float acc[4][2][4];
#pragma unroll
        for (int mf = 0; mf < 4; ++mf)
#pragma unroll
            for (int nf = 0; nf < 2; ++nf)
#pragma unroll
                for (int c = 0; c < 4; ++c) acc[mf][nf][c] = 0.f;

#pragma unroll
        for (int kk = 0; kk < 16; ++kk) {
            const uint32_t offA = (uint32_t)(((2 * kk + aDu) ^ xL) << 4);
            const uint32_t offB = (uint32_t)(((2 * kk + bDu) ^ xL) << 4);
            unsigned b[4];
            ldsm4(b, bBase + offB);
#pragma unroll
            for (int mf = 0; mf < 4; ++mf) {
                unsigned a[4];
                ldsm4(a, aBase[mf] + offA);
                mma_bf16(acc[mf][0], a, b[0], b[1]);
                mma_bf16(acc[mf][1], a, b[2], b[3]);
            }
        }
        __syncthreads();   // all warps done reading WQ

        // restage WQ: Wp half 1 (h==0) or q tile (h==1) — overlaps epilogue
        if (h == 0) {
#pragma unroll
            for (int i = 0; i < 8; ++i) {
                const int id = t + i * 512, r = id >> 5, u = id & 31;
                cp16(WQ + SWZB(r, u), &g_wpb[(size_t)(128 + r) * 256 + u * 8]);
            }
        } else {
#pragma unroll
            for (int i = 0; i < 8; ++i) {
                const int id = t + i * 512, r = id >> 5, u = id & 31;
                cp16(WQ + SWZB(r, u), &g_qb[((size_t)n * L_Q + r) * 256 + u * 8]);
            }
        }
        cp_commit();

        // epilogue: +bias, sum-sq, store bf16 kp tile
#pragma unroll
        for (int mf = 0; mf < 4; ++mf) {
            const int m0 = wm * 64 + mf * 16 + g, m1 = m0 + 8;
            float ss0 = 0.f, ss1 = 0.f;
#pragma unroll
            for (int nf = 0; nf < 2; ++nf) {
                const int jc = h * 128 + wn * 16 + nf * 8 + 2 * tid4;
                const float b0v = bsm[jc], b1v = bsm[jc + 1];
                const float v00 = acc[mf][nf][0] + b0v, v01 = acc[mf][nf][1] + b1v;
                const float v10 = acc[mf][nf][2] + b0v, v11 = acc[mf][nf][3] + b1v;
                ss0 += v00 * v00 + v01 * v01;
                ss1 += v10 * v10 + v11 * v11;
                *(unsigned*)(KP + KPB(m0, jc)) = pkbf(v00, v01);
                *(unsigned*)(KP + KPB(m1, jc)) = pkbf(v10, v11);
            }
            ss0 += __shfl_xor_sync(0xffffffffu, ss0, 1);
            ss0 += __shfl_xor_sync(0xffffffffu, ss0, 2);
            ss1 += __shfl_xor_sync(0xffffffffu, ss1, 1);
            ss1 += __shfl_xor_sync(0xffffffffu, ss1, 2);
            if (tid4 == 0) {
                atomicAdd(&rowss[m0], ss0);
                atomicAdd(&rowss[m1], ss1);
            }
        }
    }
    __syncthreads();
    if (t < 128) rowss[t] = 1.0f / fmaxf(sqrtf(rowss[t]), 1e-12f);
    cp_wait0();        // q tile staged
    __syncthreads();

    // ================= Phase 2: logits[s][l] = (KP . q) * invnorm[s] ============
    float acc[4][2][4];
#pragma unroll
    for (int mf = 0; mf < 4; ++mf)
#pragma unroll
        for (int nf = 0; nf < 2; ++nf)
#pragma unroll
            for (int c = 0; c < 4; ++c) acc[mf][nf][c] = 0.f;

#pragma unroll
    for (int kk = 0; kk < 16; ++kk) {
        const uint32_t offA = (uint32_t)(((2 * kk + aDu) ^ xL) << 4);
        const uint32_t offB = (uint32_t)(((2 * kk + bDu) ^ xL) << 4);
        unsigned b[4];
        ldsm4(b, bBase + offB);
#pragma unroll
        for (int mf = 0; mf < 4; ++mf) {
            unsigned a[4];
            ldsm4(a, kpBase[mf] + offA);
            mma_bf16(acc[mf][0], a, b[0], b[1]);
            mma_bf16(acc[mf][1], a, b[2], b[3]);
        }
    }

    // scale by 1/norm (rows = s)
#pragma unroll
    for (int mf = 0; mf < 4; ++mf) {
        const int r0 = wm * 64 + mf * 16 + g;
        const float inv0 = rowss[r0], inv1 = rowss[r0 + 8];
#pragma unroll
        for (int nf = 0; nf < 2; ++nf) {
            acc[mf][nf][0] *= inv0; acc[mf][nf][1] *= inv0;
            acc[mf][nf][2] *= inv1; acc[mf][nf][3] *= inv1;
        }
    }

    // CTA-local per-l max
#pragma unroll
    for (int nf = 0; nf < 2; ++nf) {
        float me = acc[0][nf][0], mo = acc[0][nf][1];
#pragma unroll
        for (int mf = 0; mf < 4; ++mf) {
            me = fmaxf(me, fmaxf(acc[mf][nf][0], acc[mf][nf][2]));
            mo = fmaxf(mo, fmaxf(acc[mf][nf][1], acc[mf][nf][3]));
        }
#pragma unroll
        for (int off = 4; off < 32; off <<= 1) {
            me = fmaxf(me, __shfl_xor_sync(0xffffffffu, me, off));
            mo = fmaxf(mo, __shfl_xor_sync(0xffffffffu, mo, off));
        }
        if (lane < 4) {
            const int lc = wn * 16 + nf * 8 + 2 * lane;
            atomicMax(&amax_s[lc],     fmap(me));
            atomicMax(&amax_s[lc + 1], fmap(mo));
        }
    }
    __syncthreads();
    if (t < 128) {
        atomicMax(&g_amax[t * 8 + n], amax_s[t]);
        thr_s[t] = funmap(amax_s[t]) - MARGIN;
    }
    __syncthreads();

    // candidate count + scan + pool write
    int cnt = 0;
#pragma unroll
    for (int mf = 0; mf < 4; ++mf)
#pragma unroll
        for (int nf = 0; nf < 2; ++nf)
#pragma unroll
            for (int c = 0; c < 4; ++c) {
                const int lc = wn * 16 + nf * 8 + 2 * tid4 + (c & 1);
                if (acc[mf][nf][c] >= thr_s[lc]) ++cnt;
            }
    int incl = cnt;
#pragma unroll
    for (int off = 1; off < 32; off <<= 1) {
        const int x = __shfl_up_sync(0xffffffffu, incl, off);
        if (lane >= off) incl += x;
    }
    if (lane == 31) wtot[wid] = (unsigned)incl;
    __syncthreads();
    if (t == 0) {
        unsigned tot = 0;
#pragma unroll
        for (int w = 0; w < 16; ++w) { woff[w] = tot; tot += wtot[w]; }
        *base_s = atomicAdd(&g_npool, tot);
    }
    __syncthreads();
    unsigned p = *base_s + woff[wid] + (unsigned)(incl - cnt);
#pragma unroll
    for (int mf = 0; mf < 4; ++mf)
#pragma unroll
        for (int nf = 0; nf < 2; ++nf)
#pragma unroll
            for (int c = 0; c < 4; ++c) {
                const int lc = wn * 16 + nf * 8 + 2 * tid4 + (c & 1);
                const float v = acc[mf][nf][c];
                if (v >= thr_s[lc]) {
                    const int sr = s0 + wm * 64 + mf * 16 + g + ((c >= 2) ? 8 : 0);
                    if (p < POOL_CAP)
                        g_pool[p] = make_uint2(((unsigned)sr << 10) |
                                               ((unsigned)lc << 3) | (unsigned)n,
                                               __float_as_uint(v));
                    ++p;
                }
            }
}

// ---------------- K4: filter pool against global approx max ----------------
__global__ __launch_bounds__(256) void filter_kernel()
{
    __shared__ float thr_s[LN_ROWS];
    const int t = threadIdx.x;
    for (int i = t; i < LN_ROWS; i += 256) thr_s[i] = funmap(g_amax[i]) - MARGIN;
    __syncthreads();
    const unsigned np = min(g_npool, (unsigned)POOL_CAP);
    for (unsigned idx = blockIdx.x * 256 + t; idx < np; idx += gridDim.x * 256) {
        const uint2 e = g_pool[idx];
        const unsigned l = (e.x >> 3) & 127u, n = e.x & 7u;
        if (__uint_as_float(e.y) >= thr_s[l * 8 + n]) {
            const unsigned pp = atomicAdd(&g_ncand, 1u);
            if (pp < CAND_CAP) g_cand[pp] = e.x;
        }
    }
}

// ---------------- K5: exact fp32 rescore, batched 32 candidates/CTA ----------------
#define RS_SMEM (32768 + 32896 + 32896)
__global__ __launch_bounds__(256, 1) void rescore_kernel(
    const float* __restrict__ mem, const float* __restrict__ pos,
    const float* __restrict__ Wp,  const float* __restrict__ bp)
{
    extern __shared__ char rsm[];
    float* A   = (float*)rsm;                    // [32][256]
    float* WT  = (float*)(rsm + 32768);          // [kk][o], stride 257
    float* KPS = (float*)(rsm + 65664);          // [ci][t], stride 257
    __shared__ unsigned meta[32];
    __shared__ unsigned count_s;

    const int t = threadIdx.x, lane = t & 31, wid = t >> 5;
    if (t == 0) count_s = min(g_ncand, (unsigned)CAND_CAP);
    __syncthreads();
    const unsigned count = count_s;
    const unsigned nchunks = (count + 31u) >> 5;

    for (unsigned chunk = blockIdx.x; chunk < nchunks; chunk += gridDim.x) {
        __syncthreads();
        if (t < 32)
            meta[t] = (chunk * 32u + t < count) ? g_cand[chunk * 32u + t] : 0xFFFFFFFFu;
        __syncthreads();
#pragma unroll 4
        for (int ci = 0; ci < 32; ++ci) {
            const unsigned pk = meta[ci];
            if (pk != 0xFFFFFFFFu) {
                const size_t rowk = ((size_t)(pk >> 10) * 8 + (pk & 7u)) * 256;
                A[ci * 256 + t] = mem[rowk + t] + pos[rowk + t];
            }
        }
        float acc[32];
        const float bias = bp[t];
#pragma unroll
        for (int ci = 0; ci < 32; ++ci) acc[ci] = bias;

        for (int kt = 0; kt < 8; ++kt) {
            __syncthreads();
#pragma unroll
            for (int i = 0; i < 8; ++i) {
                const int id = t + i * 256, o = id >> 3, k4 = id & 7;
                const float4 w = *(const float4*)&Wp[(size_t)o * 256 + kt * 32 + k4 * 4];
                WT[(k4 * 4 + 0) * 257 + o] = w.x;
                WT[(k4 * 4 + 1) * 257 + o] = w.y;
                WT[(k4 * 4 + 2) * 257 + o] = w.z;
                WT[(k4 * 4 + 3) * 257 + o] = w.w;
            }
            __syncthreads();
            float wt[32];
#pragma unroll
            for (int kk = 0; kk < 32; ++kk) wt[kk] = WT[kk * 257 + t];
#pragma unroll 4
            for (int ci = 0; ci < 32; ++ci) {
                const float4* a4 = (const float4*)&A[ci * 256 + kt * 32];
#pragma unroll
                for (int q = 0; q < 8; ++q) {
                    const float4 av = a4[q];
                    acc[ci] += av.x * wt[q * 4 + 0] + av.y * wt[q * 4 + 1]
                             + av.z * wt[q * 4 + 2] + av.w * wt[q * 4 + 3];
                }
            }
        }
        __syncthreads();
#pragma unroll
        for (int ci = 0; ci < 32; ++ci) KPS[ci * 257 + t] = acc[ci];
        __syncthreads();
#pragma unroll
        for (int cc = 0; cc < 4; ++cc) {
            const int ci = wid * 4 + cc;
            const unsigned pk = meta[ci];
            if (pk == 0xFFFFFFFFu) continue;
            const unsigned s = pk >> 10, l = (pk >> 3) & 127u, n = pk & 7u;
            const float* qrow = &g_qproj[((size_t)l * 8 + n) * 256];
            float ss = 0.f, qd = 0.f;
#pragma unroll
            for (int j = 0; j < 8; ++j) {
                const float kv = KPS[ci * 257 + lane + 32 * j];
                ss += kv * kv;
                qd += qrow[lane + 32 * j] * kv;
            }
#pragma unroll
            for (int off = 16; off > 0; off >>= 1) {
                ss += __shfl_xor_sync(0xffffffffu, ss, off);
                qd += __shfl_xor_sync(0xffffffffu, qd, off);
            }
            if (lane == 0) {
                const float logit = qd / fmaxf(sqrtf(ss), 1e-12f);
                const unsigned long long key =
                    ((unsigned long long)fmap(logit) << 32) |
                    (unsigned long long)(0xFFFFFFFFu - s);
                atomicMax(&g_argmax[l * 8 + n], key);
            }
        }
    }
}

// ---------------- K6: batched finalize — 64 CTAs x 16 rows ----------------
#define FIN_SMEM (16384 + 16384 + 32896)
__global__ __launch_bounds__(256, 1) void finalize_kernel(
    const float* __restrict__ tgt,   const float* __restrict__ memory,
    const float* __restrict__ pos,
    const float* __restrict__ Wp,    const float* __restrict__ bp,
    const float* __restrict__ Wv,    const float* __restrict__ bv,
    const float* __restrict__ Wo,    const float* __restrict__ bo,
    const float* __restrict__ gamma, const float* __restrict__ beta,
    float* __restrict__ out)
{
    extern __shared__ char fsm[];
    float* BUF0 = (float*)fsm;                    // [16][256]
    float* BUF1 = (float*)(fsm + 16384);          // [16][256]
    float* WT   = (float*)(fsm + 32768);          // [32][257]
    __shared__ int sel_s[16];

    const int t = threadIdx.x, lane = t & 31, wid = t >> 5;
    const int base = blockIdx.x * 16;

    if (t < 16) {
        const unsigned long long key = g_argmax[base + t];
        sel_s[t] = (int)(0xFFFFFFFFu - (unsigned)(key & 0xFFFFFFFFull));
    }
    __syncthreads();
#pragma unroll
    for (int r = 0; r < 16; ++r) {
        const size_t rowk = ((size_t)sel_s[r] * 8 + ((base + r) & 7)) * 256;
        BUF0[r * 256 + t] = memory[rowk + t] + pos[rowk + t];
    }
    const float* Ws[3] = {Wp, Wv, Wo};
    const float* bs[3] = {bp, bv, bo};
#pragma unroll
    for (int layer = 0; layer < 3; ++layer) {
        const float* W   = Ws[layer];
        float* INB  = (layer & 1) ? BUF1 : BUF0;
        float* OUTB = (layer & 1) ? BUF0 : BUF1;
        float acc[16];
#pragma unroll
        for (int r = 0; r < 16; ++r) acc[r] = 0.f;
        for (int kt = 0; kt < 8; ++kt) {
            __syncthreads();
#pragma unroll
            for (int i = 0; i < 8; ++i) {
                const int id = t + i * 256, o = id >> 3, k4 = id & 7;
                const float4 w = *(const float4*)&W[(size_t)o * 256 + kt * 32 + k4 * 4];
                WT[(k4 * 4 + 0) * 257 + o] = w.x;
                WT[(k4 * 4 + 1) * 257 + o] = w.y;
                WT[(k4 * 4 + 2) * 257 + o] = w.z;
                WT[(k4 * 4 + 3) * 257 + o] = w.w;
            }
            __syncthreads();
            float wt[32];
#pragma unroll
            for (int kk = 0; kk < 32; ++kk) wt[kk] = WT[kk * 257 + t];
#pragma unroll
            for (int r = 0; r < 16; ++r) {
                const float4* a4 = (const float4*)&INB[r * 256 + kt * 32];
#pragma unroll
                for (int q = 0; q < 8; ++q) {
                    const float4 av = a4[q];
                    acc[r] += av.x * wt[q * 4 + 0] + av.y * wt[q * 4 + 1]
                            + av.z * wt[q * 4 + 2] + av.w * wt[q * 4 + 3];
                }
            }
        }
        __syncthreads();
        const float bias = bs[layer][t];
#pragma unroll
        for (int r = 0; r < 16; ++r)
            OUTB[r * 256 + t] = acc[r] + bias;
    }
    __syncthreads();
#pragma unroll
    for (int rr = 0; rr < 2; ++rr) {
        const int r = wid * 2 + rr;
        const int pair = base + r;
        float xv[8];
        float s = 0.f, s2 = 0.f;
#pragma unroll
        for (int j = 0; j < 8; ++j) {
            const int c = lane + 32 * j;
            xv[j] = tgt[(size_t)pair * 256 + c] + BUF1[r * 256 + c];
            s  += xv[j];
            s2 += xv[j] * xv[j];
        }
#pragma unroll
        for (int off = 16; off > 0; off >>= 1) {
            s  += __shfl_xor_sync(0xffffffffu, s,  off);
            s2 += __shfl_xor_sync(0xffffffffu, s2, off);
        }
        const float mu   = s * (1.0f / 256.0f);
        const float var  = s2 * (1.0f / 256.0f) - mu * mu;
        const float rstd = rsqrtf(var + 1e-5f);
#pragma unroll
        for (int j = 0; j < 8; ++j) {
            const int c = lane + 32 * j;
            out[(size_t)pair * 256 + c] = (xv[j] - mu) * rstd * gamma[c] + beta[c];
        }
    }
}

// ---------------- launch ----------------
extern "C" void kernel_launch(void* const* d_in, const int* in_sizes, int n_in,
                              void* d_out, int out_size)
{
    const float* tgt       = (const float*)d_in[0];
    const float* memory    = (const float*)d_in[1];
    const float* pos       = (const float*)d_in[2];
    const float* query_pos = (const float*)d_in[3];
    const float* Wq        = (const float*)d_in[4];
    const float* bq        = (const float*)d_in[5];
    const float* Wp        = (const float*)d_in[6];
    const float* bp        = (const float*)d_in[7];
    const float* Wv        = (const float*)d_in[8];
    const float* bv        = (const float*)d_in[9];
    const float* Wo        = (const float*)d_in[10];
    const float* bo        = (const float*)d_in[11];
    const float* gamma     = (const float*)d_in[12];
    const float* beta      = (const float*)d_in[13];
    float* out             = (float*)d_out;

    cudaFuncSetAttribute(fused_kernel,
                         cudaFuncAttributeMaxDynamicSharedMemorySize, FU_SMEM);
    cudaFuncSetAttribute(rescore_kernel,
                         cudaFuncAttributeMaxDynamicSharedMemorySize, RS_SMEM);
    cudaFuncSetAttribute(finalize_kernel,
                         cudaFuncAttributeMaxDynamicSharedMemorySize, FIN_SMEM);

    init_kernel<<<256, 256>>>(Wp);
    qproj_kernel<<<LN_ROWS / 8, 256>>>(tgt, query_pos, Wq, bq);
    fused_kernel<<<dim3(S_P / 128, N_B), 512, FU_SMEM>>>(memory, pos, bp);
    filter_kernel<<<512, 256>>>();
    rescore_kernel<<<148, 256, RS_SMEM>>>(memory, pos, Wp, bp);
    finalize_kernel<<<LN_ROWS / 16, 256, FIN_SMEM>>>(tgt, memory, pos, Wp, bp,
                                                     Wv, bv, Wo, bo,
                                                     gamma, beta, out);
}